// round 4
// baseline (speedup 1.0000x reference)
#include <cuda_runtime.h>
#include <cuda_bf16.h>
#include <cstdint>

#define N_MAX   50000
#define E_MAX   800000
#define G_CNT   512
#define FDIM    128
#define OUTD    200
#define SCAN_B  1024

// ---------------- device scratch (static, no allocation) ----------------
__device__ __align__(128) float g_x[N_MAX * FDIM];     // ping
__device__ __align__(128) float g_agg[N_MAX * FDIM];   // pong
__device__ int   g_deg[2 * N_MAX];                     // [0..N)=deg_out, [N..2N)=deg_in
__device__ float g_norm_out[N_MAX];
__device__ float g_norm_in[N_MAX];
__device__ int   g_row_off[N_MAX + 1];
__device__ int   g_cursor[N_MAX];
__device__ int   g_esrc[E_MAX];
__device__ int   g_bsum[64];

// ---------------- setup kernels ----------------

__global__ void k_zero_deg(int n2) {
    for (int i = blockIdx.x * blockDim.x + threadIdx.x; i < n2; i += gridDim.x * blockDim.x)
        g_deg[i] = 0;
}

__global__ void k_deg(const int* __restrict__ src, const int* __restrict__ dst, int E, int n) {
    for (int e = blockIdx.x * blockDim.x + threadIdx.x; e < E; e += gridDim.x * blockDim.x) {
        atomicAdd(&g_deg[src[e]], 1);
        atomicAdd(&g_deg[n + dst[e]], 1);
    }
}

// Per-block inclusive scan of deg_in -> g_row_off[i+1] (block-local), totals -> g_bsum.
// Fuses norm computation and cursor zeroing.
__global__ void __launch_bounds__(SCAN_B) k_scan1(int n) {
    __shared__ int wsum[32];
    const int tid = threadIdx.x, lane = tid & 31, wid = tid >> 5;
    const int i = blockIdx.x * SCAN_B + tid;
    int v = 0;
    if (i < n) {
        v = g_deg[n + i];
        g_cursor[i] = 0;
        g_norm_out[i] = rsqrtf(fmaxf((float)g_deg[i], 1.0f));
        g_norm_in[i]  = rsqrtf(fmaxf((float)v, 1.0f));
    }
    int x = v;
    #pragma unroll
    for (int off = 1; off < 32; off <<= 1) {
        int t = __shfl_up_sync(0xffffffffu, x, off);
        if (lane >= off) x += t;
    }
    if (lane == 31) wsum[wid] = x;
    __syncthreads();
    if (wid == 0) {
        int w = wsum[lane];
        #pragma unroll
        for (int off = 1; off < 32; off <<= 1) {
            int t = __shfl_up_sync(0xffffffffu, w, off);
            if (lane >= off) w += t;
        }
        wsum[lane] = w;
    }
    __syncthreads();
    int incl = x + (wid > 0 ? wsum[wid - 1] : 0);
    if (i < n) g_row_off[i + 1] = incl;
    if (tid == SCAN_B - 1) g_bsum[blockIdx.x] = incl;
    if (i == 0) g_row_off[0] = 0;
}

// Each block computes its own exclusive prefix of the (<=64) block sums, then adds.
__global__ void __launch_bounds__(SCAN_B) k_scan3(int n, int nb) {
    __shared__ int soff;
    if (threadIdx.x < 32) {
        int l = threadIdx.x;
        int bid = blockIdx.x;
        int v = (l < nb && l < bid) ? g_bsum[l] : 0;
        if (l + 32 < nb && l + 32 < bid) v += g_bsum[l + 32];
        #pragma unroll
        for (int off = 16; off > 0; off >>= 1)
            v += __shfl_down_sync(0xffffffffu, v, off);
        if (l == 0) soff = v;
    }
    __syncthreads();
    int i = blockIdx.x * SCAN_B + threadIdx.x;
    if (i < n) g_row_off[i + 1] += soff;
}

__global__ void k_fill(const int* __restrict__ src, const int* __restrict__ dst, int E) {
    for (int e = blockIdx.x * blockDim.x + threadIdx.x; e < E; e += gridDim.x * blockDim.x) {
        int d = dst[e];
        int p = g_row_off[d] + atomicAdd(&g_cursor[d], 1);
        g_esrc[p] = src[e];
    }
}

// x = concat(init_embed[nid], z_table[z]) * norm_out[node]
__global__ void k_features(const int* __restrict__ nid, const int* __restrict__ z,
                           const float* __restrict__ init_embed,
                           const float* __restrict__ z_table, int n) {
    int total = n * 32;
    for (int idx = blockIdx.x * blockDim.x + threadIdx.x; idx < total; idx += gridDim.x * blockDim.x) {
        int node = idx >> 5, q = idx & 31;
        float4 v;
        if (q < 16) v = __ldg(&((const float4*)init_embed)[(long)nid[node] * 16 + q]);
        else        v = __ldg(&((const float4*)z_table)[(long)z[node] * 16 + (q - 16)]);
        float s = g_norm_out[node];
        ((float4*)g_x)[node * 32 + q] = make_float4(v.x * s, v.y * s, v.z * s, v.w * s);
    }
}

// ---------------- fused SpMM + GEMM ----------------
// One block = 128 output rows. Phase 1: gather-aggregate the 128 rows of
// A = norm_in * (adjacency-gather of xin) straight into smem (paired-k layout).
// Phase 2: f32x2-packed GEMM out of smem: xout = act(A @ W + b) [* norm_out].
// xin/xout ping-pong between g_x and g_agg (no intra-kernel RAW on xin).
//
// smem: As2[128][66] float2  (row-major, kpair inner, pad 2)   67584 B
//       Bs2[64][130] float2  (kpair-major, col inner, pad 2)   66560 B
#define AS_LD 66
#define BS_LD 130
#define FUSED_SMEM (128 * AS_LD * 8 + 64 * BS_LD * 8)

__global__ void __launch_bounds__(512) k_fused(const float* __restrict__ W,
                                               const float* __restrict__ bias,
                                               int n, int relu, int scaleOut, int pp) {
    extern __shared__ char smem[];
    float2* As2 = (float2*)smem;                    // [128][AS_LD]
    float2* Bs2 = As2 + 128 * AS_LD;                // [64][BS_LD]

    const float* xin  = pp ? g_agg : g_x;
    float*       xout = pp ? g_x   : g_agg;

    const int tid  = threadIdx.x;
    const int lane = tid & 31;
    const int w    = tid >> 5;          // warp 0..15
    const int row0 = blockIdx.x * 128;

    // ---- stage W into registers (overlaps with gather) ----
    // thread: col = tid&127, kpair group = (tid>>7)*16 .. +15
    const int wcol = tid & 127;
    const int wkp0 = (tid >> 7) * 16;
    float we[16], wo[16];
    #pragma unroll
    for (int t = 0; t < 16; t++) {
        we[t] = __ldg(&W[(2 * (wkp0 + t))     * FDIM + wcol]);
        wo[t] = __ldg(&W[(2 * (wkp0 + t) + 1) * FDIM + wcol]);
    }

    // ---- phase 1: gather 8 rows per warp ----
    const float4* x4 = (const float4*)xin;
    #pragma unroll 1
    for (int rr = 0; rr < 8; rr++) {
        int r = w * 8 + rr;
        int grow = row0 + r;
        float4 a = make_float4(0.f, 0.f, 0.f, 0.f);
        if (grow < n) {
            int e0 = __ldg(&g_row_off[grow]);
            int e1 = __ldg(&g_row_off[grow + 1]);
            float4 b = make_float4(0.f, 0.f, 0.f, 0.f);
            int e = e0;
            for (; e + 7 < e1; e += 8) {
                int s0 = __ldg(&g_esrc[e + 0]), s1 = __ldg(&g_esrc[e + 1]);
                int s2 = __ldg(&g_esrc[e + 2]), s3 = __ldg(&g_esrc[e + 3]);
                int s4 = __ldg(&g_esrc[e + 4]), s5 = __ldg(&g_esrc[e + 5]);
                int s6 = __ldg(&g_esrc[e + 6]), s7 = __ldg(&g_esrc[e + 7]);
                float4 v0 = __ldg(&x4[s0 * 32 + lane]);
                float4 v1 = __ldg(&x4[s1 * 32 + lane]);
                float4 v2 = __ldg(&x4[s2 * 32 + lane]);
                float4 v3 = __ldg(&x4[s3 * 32 + lane]);
                float4 v4 = __ldg(&x4[s4 * 32 + lane]);
                float4 v5 = __ldg(&x4[s5 * 32 + lane]);
                float4 v6 = __ldg(&x4[s6 * 32 + lane]);
                float4 v7 = __ldg(&x4[s7 * 32 + lane]);
                a.x += v0.x + v1.x + v2.x + v3.x;
                a.y += v0.y + v1.y + v2.y + v3.y;
                a.z += v0.z + v1.z + v2.z + v3.z;
                a.w += v0.w + v1.w + v2.w + v3.w;
                b.x += v4.x + v5.x + v6.x + v7.x;
                b.y += v4.y + v5.y + v6.y + v7.y;
                b.z += v4.z + v5.z + v6.z + v7.z;
                b.w += v4.w + v5.w + v6.w + v7.w;
            }
            for (; e < e1; e++) {
                int s0 = __ldg(&g_esrc[e]);
                float4 v0 = __ldg(&x4[s0 * 32 + lane]);
                a.x += v0.x; a.y += v0.y; a.z += v0.z; a.w += v0.w;
            }
            float ni = __ldg(&g_norm_in[grow]);
            a.x = (a.x + b.x) * ni;
            a.y = (a.y + b.y) * ni;
            a.z = (a.z + b.z) * ni;
            a.w = (a.w + b.w) * ni;
        }
        // paired-k write: lane owns kpairs {2*lane, 2*lane+1} = one float4, conflict-free
        *(float4*)&As2[r * AS_LD + lane * 2] = a;
    }

    // ---- stage W regs into smem ----
    #pragma unroll
    for (int t = 0; t < 16; t++)
        Bs2[(wkp0 + t) * BS_LD + wcol] = make_float2(we[t], wo[t]);

    __syncthreads();

    // ---- phase 2: GEMM ----
    // thread (tm=tid>>4, tn=tid&15): rows tm*4..+3, cols {tn*4..+3} and {64+tn*4..+3}
    const int tn = tid & 15;
    const int tm = tid >> 4;

    unsigned long long acc[4][8];
    #pragma unroll
    for (int i = 0; i < 4; i++)
        #pragma unroll
        for (int j = 0; j < 8; j++) acc[i][j] = 0ull;

    #pragma unroll 4
    for (int kp = 0; kp < 64; kp += 2) {
        unsigned long long ae[4], ao[4];
        #pragma unroll
        for (int i = 0; i < 4; i++) {
            ulonglong2 t = *(const ulonglong2*)&As2[(tm * 4 + i) * AS_LD + kp];
            ae[i] = t.x; ao[i] = t.y;
        }
        unsigned long long be[8], bo[8];
        {
            ulonglong2 t0 = *(const ulonglong2*)&Bs2[kp * BS_LD + tn * 4];
            ulonglong2 t1 = *(const ulonglong2*)&Bs2[kp * BS_LD + tn * 4 + 2];
            ulonglong2 t2 = *(const ulonglong2*)&Bs2[kp * BS_LD + 64 + tn * 4];
            ulonglong2 t3 = *(const ulonglong2*)&Bs2[kp * BS_LD + 64 + tn * 4 + 2];
            be[0] = t0.x; be[1] = t0.y; be[2] = t1.x; be[3] = t1.y;
            be[4] = t2.x; be[5] = t2.y; be[6] = t3.x; be[7] = t3.y;
            ulonglong2 u0 = *(const ulonglong2*)&Bs2[(kp + 1) * BS_LD + tn * 4];
            ulonglong2 u1 = *(const ulonglong2*)&Bs2[(kp + 1) * BS_LD + tn * 4 + 2];
            ulonglong2 u2 = *(const ulonglong2*)&Bs2[(kp + 1) * BS_LD + 64 + tn * 4];
            ulonglong2 u3 = *(const ulonglong2*)&Bs2[(kp + 1) * BS_LD + 64 + tn * 4 + 2];
            bo[0] = u0.x; bo[1] = u0.y; bo[2] = u1.x; bo[3] = u1.y;
            bo[4] = u2.x; bo[5] = u2.y; bo[6] = u3.x; bo[7] = u3.y;
        }
        #pragma unroll
        for (int i = 0; i < 4; i++)
            #pragma unroll
            for (int j = 0; j < 8; j++) {
                asm("fma.rn.f32x2 %0, %1, %2, %0;" : "+l"(acc[i][j]) : "l"(ae[i]), "l"(be[j]));
                asm("fma.rn.f32x2 %0, %1, %2, %0;" : "+l"(acc[i][j]) : "l"(ao[i]), "l"(bo[j]));
            }
    }

    // ---- epilogue ----
    float bb[8];
    #pragma unroll
    for (int q = 0; q < 4; q++) {
        bb[q]     = __ldg(&bias[tn * 4 + q]);
        bb[4 + q] = __ldg(&bias[64 + tn * 4 + q]);
    }
    #pragma unroll
    for (int i = 0; i < 4; i++) {
        int grow = row0 + tm * 4 + i;
        if (grow >= n) break;
        float s = scaleOut ? g_norm_out[grow] : 1.0f;
        float o[8];
        #pragma unroll
        for (int j = 0; j < 8; j++) {
            float2 p = *(float2*)&acc[i][j];
            float v = p.x + p.y + bb[j];
            if (relu) v = fmaxf(v, 0.f);
            o[j] = v * s;
        }
        *(float4*)&xout[grow * FDIM + tn * 4]      = make_float4(o[0], o[1], o[2], o[3]);
        *(float4*)&xout[grow * FDIM + 64 + tn * 4] = make_float4(o[4], o[5], o[6], o[7]);
    }
}

// ---------------- fused pooling + MLP head (reads g_agg) ----------------
__global__ void __launch_bounds__(256) k_pool_mlp(const int* __restrict__ gid, int n,
                                                  const float* __restrict__ lin1_W,
                                                  const float* __restrict__ lin1_b,
                                                  const float* __restrict__ lin2_W,
                                                  const float* __restrict__ lin2_b,
                                                  float* __restrict__ out) {
    __shared__ float gs[FDIM];
    __shared__ float hs[FDIM];
    __shared__ int s_lo, s_hi;
    const int g = blockIdx.x;
    const int tid = threadIdx.x;

    if (tid == 0) {
        int lo = 0, hi = n;
        while (lo < hi) { int m = (lo + hi) >> 1; if (__ldg(&gid[m]) < g) lo = m + 1; else hi = m; }
        s_lo = lo;
    } else if (tid == 32) {
        int lo = 0, hi = n;
        while (lo < hi) { int m = (lo + hi) >> 1; if (__ldg(&gid[m]) <= g) lo = m + 1; else hi = m; }
        s_hi = lo;
    }
    __syncthreads();

    const int lo = s_lo, hi = s_hi;
    if (tid < FDIM) {
        float acc = 0.f;
        for (int node = lo; node < hi; node++)
            acc += g_agg[node * FDIM + tid];
        gs[tid] = acc;
    }
    __syncthreads();
    if (tid < FDIM) {
        float acc = __ldg(&lin1_b[tid]);
        #pragma unroll 8
        for (int k = 0; k < FDIM; k++)
            acc += gs[k] * __ldg(&lin1_W[k * FDIM + tid]);
        hs[tid] = fmaxf(acc, 0.f);
    }
    __syncthreads();
    for (int c = tid; c < OUTD; c += blockDim.x) {
        float acc = __ldg(&lin2_b[c]);
        #pragma unroll 8
        for (int k = 0; k < FDIM; k++)
            acc += hs[k] * __ldg(&lin2_W[k * OUTD + c]);
        out[g * OUTD + c] = acc;
    }
}

// ---------------- launch ----------------
extern "C" void kernel_launch(void* const* d_in, const int* in_sizes, int n_in,
                              void* d_out, int out_size) {
    const int*   nid        = (const int*)  d_in[0];
    const int*   z          = (const int*)  d_in[1];
    const int*   src        = (const int*)  d_in[2];
    const int*   dst        = (const int*)  d_in[3];
    const int*   graph_id   = (const int*)  d_in[4];
    const float* init_embed = (const float*)d_in[5];
    const float* z_table    = (const float*)d_in[6];
    const float* W0 = (const float*)d_in[7];
    const float* b0 = (const float*)d_in[8];
    const float* W1 = (const float*)d_in[9];
    const float* b1 = (const float*)d_in[10];
    const float* W2 = (const float*)d_in[11];
    const float* b2 = (const float*)d_in[12];
    const float* lin1_W = (const float*)d_in[13];
    const float* lin1_b = (const float*)d_in[14];
    const float* lin2_W = (const float*)d_in[15];
    const float* lin2_b = (const float*)d_in[16];
    float* out = (float*)d_out;

    const int n = in_sizes[0];       // 50000
    const int E = in_sizes[2];       // 800000
    const int nb = (n + SCAN_B - 1) / SCAN_B;

    cudaFuncSetAttribute(k_fused, cudaFuncAttributeMaxDynamicSharedMemorySize, FUSED_SMEM);

    // 1) degrees
    k_zero_deg<<<256, 256>>>(2 * n);
    k_deg<<<(E + 511) / 512, 512>>>(src, dst, E, n);

    // 2) norms + CSR row offsets (2-phase scan), then fill
    k_scan1<<<nb, SCAN_B>>>(n);
    k_scan3<<<nb, SCAN_B>>>(n, nb);
    k_fill<<<(E + 511) / 512, 512>>>(src, dst, E);

    // 3) node features (pre-scaled by norm_out)
    k_features<<<(n * 32 + 255) / 256, 256>>>(nid, z, init_embed, z_table, n);

    // 4) 3 fused GCN layers (ping-pong g_x <-> g_agg)
    const int fb = (n + 127) / 128;
    k_fused<<<fb, 512, FUSED_SMEM>>>(W0, b0, n, 1, 1, 0);  // g_x  -> g_agg
    k_fused<<<fb, 512, FUSED_SMEM>>>(W1, b1, n, 1, 1, 1);  // g_agg-> g_x
    k_fused<<<fb, 512, FUSED_SMEM>>>(W2, b2, n, 0, 0, 0);  // g_x  -> g_agg

    // 5) fused pooling + MLP head
    k_pool_mlp<<<G_CNT, 256>>>(graph_id, n, lin1_W, lin1_b, lin2_W, lin2_b, out);
}

// round 5
// speedup vs baseline: 1.3200x; 1.3200x over previous
#include <cuda_runtime.h>
#include <cuda_fp16.h>
#include <cstdint>

#define N_MAX   50000
#define E_MAX   800000
#define G_CNT   512
#define FDIM    128
#define OUTD    200
#define SCAN_B  1024

// ---------------- device scratch (static, no allocation) ----------------
__device__ __align__(128) __half g_xh[N_MAX * FDIM];   // half features (SpMM input), pre-scaled by norm_out
__device__ __align__(128) float  g_agg[N_MAX * FDIM];  // fp32 aggregated (GEMM input)
__device__ __align__(128) float  g_xf[N_MAX * FDIM];   // fp32 final layer output (pool input)
__device__ int   g_deg[2 * N_MAX];
__device__ float g_norm_out[N_MAX];
__device__ float g_norm_in[N_MAX];
__device__ int   g_row_off[N_MAX + 1];
__device__ int   g_cursor[N_MAX];
__device__ int   g_esrc[E_MAX];
__device__ int   g_bsum[64];

// ---------------- setup kernels ----------------

__global__ void k_zero_deg(int n2) {
    for (int i = blockIdx.x * blockDim.x + threadIdx.x; i < n2; i += gridDim.x * blockDim.x)
        g_deg[i] = 0;
}

__global__ void k_deg(const int* __restrict__ src, const int* __restrict__ dst, int E, int n) {
    for (int e = blockIdx.x * blockDim.x + threadIdx.x; e < E; e += gridDim.x * blockDim.x) {
        atomicAdd(&g_deg[src[e]], 1);
        atomicAdd(&g_deg[n + dst[e]], 1);
    }
}

__global__ void __launch_bounds__(SCAN_B) k_scan1(int n) {
    __shared__ int wsum[32];
    const int tid = threadIdx.x, lane = tid & 31, wid = tid >> 5;
    const int i = blockIdx.x * SCAN_B + tid;
    int v = 0;
    if (i < n) {
        v = g_deg[n + i];
        g_cursor[i] = 0;
        g_norm_out[i] = rsqrtf(fmaxf((float)g_deg[i], 1.0f));
        g_norm_in[i]  = rsqrtf(fmaxf((float)v, 1.0f));
    }
    int x = v;
    #pragma unroll
    for (int off = 1; off < 32; off <<= 1) {
        int t = __shfl_up_sync(0xffffffffu, x, off);
        if (lane >= off) x += t;
    }
    if (lane == 31) wsum[wid] = x;
    __syncthreads();
    if (wid == 0) {
        int w = wsum[lane];
        #pragma unroll
        for (int off = 1; off < 32; off <<= 1) {
            int t = __shfl_up_sync(0xffffffffu, w, off);
            if (lane >= off) w += t;
        }
        wsum[lane] = w;
    }
    __syncthreads();
    int incl = x + (wid > 0 ? wsum[wid - 1] : 0);
    if (i < n) g_row_off[i + 1] = incl;
    if (tid == SCAN_B - 1) g_bsum[blockIdx.x] = incl;
    if (i == 0) g_row_off[0] = 0;
}

// Each block sums its exclusive prefix of the (<=64) block sums, then adds.
__global__ void __launch_bounds__(SCAN_B) k_scan3(int n, int nb) {
    __shared__ int soff;
    if (threadIdx.x < 32) {
        int l = threadIdx.x;
        int bid = blockIdx.x;
        int v = (l < nb && l < bid) ? g_bsum[l] : 0;
        if (l + 32 < nb && l + 32 < bid) v += g_bsum[l + 32];
        #pragma unroll
        for (int off = 16; off > 0; off >>= 1)
            v += __shfl_down_sync(0xffffffffu, v, off);
        if (l == 0) soff = v;
    }
    __syncthreads();
    int i = blockIdx.x * SCAN_B + threadIdx.x;
    if (i < n) g_row_off[i + 1] += soff;
}

__global__ void k_fill(const int* __restrict__ src, const int* __restrict__ dst, int E) {
    for (int e = blockIdx.x * blockDim.x + threadIdx.x; e < E; e += gridDim.x * blockDim.x) {
        int d = dst[e];
        int p = g_row_off[d] + atomicAdd(&g_cursor[d], 1);
        g_esrc[p] = src[e];
    }
}

// x_h = half( concat(init_embed[nid], z_table[z]) * norm_out[node] )
__global__ void k_features(const int* __restrict__ nid, const int* __restrict__ z,
                           const float* __restrict__ init_embed,
                           const float* __restrict__ z_table, int n) {
    int total = n * 32;   // 4-value units
    for (int idx = blockIdx.x * blockDim.x + threadIdx.x; idx < total; idx += gridDim.x * blockDim.x) {
        int node = idx >> 5, q = idx & 31;
        float4 v;
        if (q < 16) v = __ldg(&((const float4*)init_embed)[(long)nid[node] * 16 + q]);
        else        v = __ldg(&((const float4*)z_table)[(long)z[node] * 16 + (q - 16)]);
        float s = g_norm_out[node];
        __half2 h0 = __floats2half2_rn(v.x * s, v.y * s);
        __half2 h1 = __floats2half2_rn(v.z * s, v.w * s);
        uint2 pk;
        pk.x = *(unsigned*)&h0;
        pk.y = *(unsigned*)&h1;
        ((uint2*)g_xh)[node * 32 + q] = pk;
    }
}

// SpMM gather-reduce over half features: warp per dst node; lane = 4 halves (uint2).
// agg[d] = norm_in[d] * sum_{e in row(d)} xh[src]      (fp32 accumulation)
__global__ void __launch_bounds__(128) k_spmm(int n) {
    int warp = blockIdx.x * (blockDim.x >> 5) + (threadIdx.x >> 5);
    int lane = threadIdx.x & 31;
    if (warp >= n) return;
    int e0 = g_row_off[warp], e1 = g_row_off[warp + 1];
    float4 a0 = make_float4(0.f, 0.f, 0.f, 0.f);
    float4 a1 = a0, a2 = a0, a3 = a0;
    const uint2* xh = (const uint2*)g_xh;   // 32 uint2 per row
    int e = e0;
    for (; e + 3 < e1; e += 4) {
        int s0 = __ldg(&g_esrc[e]);
        int s1 = __ldg(&g_esrc[e + 1]);
        int s2 = __ldg(&g_esrc[e + 2]);
        int s3 = __ldg(&g_esrc[e + 3]);
        uint2 p0 = __ldg(&xh[s0 * 32 + lane]);
        uint2 p1 = __ldg(&xh[s1 * 32 + lane]);
        uint2 p2 = __ldg(&xh[s2 * 32 + lane]);
        uint2 p3 = __ldg(&xh[s3 * 32 + lane]);
        float2 f;
        f = __half22float2(*(__half2*)&p0.x); a0.x += f.x; a0.y += f.y;
        f = __half22float2(*(__half2*)&p0.y); a0.z += f.x; a0.w += f.y;
        f = __half22float2(*(__half2*)&p1.x); a1.x += f.x; a1.y += f.y;
        f = __half22float2(*(__half2*)&p1.y); a1.z += f.x; a1.w += f.y;
        f = __half22float2(*(__half2*)&p2.x); a2.x += f.x; a2.y += f.y;
        f = __half22float2(*(__half2*)&p2.y); a2.z += f.x; a2.w += f.y;
        f = __half22float2(*(__half2*)&p3.x); a3.x += f.x; a3.y += f.y;
        f = __half22float2(*(__half2*)&p3.y); a3.z += f.x; a3.w += f.y;
    }
    for (; e < e1; e++) {
        int s0 = __ldg(&g_esrc[e]);
        uint2 p0 = __ldg(&xh[s0 * 32 + lane]);
        float2 f;
        f = __half22float2(*(__half2*)&p0.x); a0.x += f.x; a0.y += f.y;
        f = __half22float2(*(__half2*)&p0.y); a0.z += f.x; a0.w += f.y;
    }
    float ni = g_norm_in[warp];
    ((float4*)g_agg)[warp * 32 + lane] =
        make_float4((a0.x + a1.x + a2.x + a3.x) * ni,
                    (a0.y + a1.y + a2.y + a3.y) * ni,
                    (a0.z + a1.z + a2.z + a3.z) * ni,
                    (a0.w + a1.w + a2.w + a3.w) * ni);
}

// Packed-FMA SGEMM using fma.rn.f32x2.
// out = act(g_agg @ W + b); layers 0/1 write half*norm_out to g_xh, layer 2 writes fp32 to g_xf.
__global__ void __launch_bounds__(256) k_gemm(const float* __restrict__ W,
                                              const float* __restrict__ bias,
                                              int n, int relu, int halfOut) {
    __shared__ __align__(16) float2 As2[8][FDIM + 2];  // [k/2][m]
    __shared__ __align__(16) float2 Bs2[8][FDIM + 2];  // [k/2][col]
    const int tid = threadIdx.x;
    const int tn = tid & 15;
    const int tm = tid >> 4;
    const int row0 = blockIdx.x * 128;

    unsigned long long acc[8][8];
    #pragma unroll
    for (int i = 0; i < 8; i++)
        #pragma unroll
        for (int j = 0; j < 8; j++) acc[i][j] = 0ull;

    float bb[8];
    #pragma unroll
    for (int j = 0; j < 8; j++) bb[j] = __ldg(&bias[tn + 16 * j]);

    const float4* A4 = (const float4*)g_agg;

    for (int k0 = 0; k0 < FDIM; k0 += 16) {
        #pragma unroll
        for (int l = 0; l < 2; l++) {
            int fid = tid + l * 256;
            int r = fid >> 2;
            int kq = fid & 3;
            int grow = row0 + r;
            float4 v = make_float4(0.f, 0.f, 0.f, 0.f);
            if (grow < n) v = A4[grow * 32 + (k0 >> 2) + kq];
            As2[kq * 2 + 0][r] = make_float2(v.x, v.y);
            As2[kq * 2 + 1][r] = make_float2(v.z, v.w);
        }
        {
            int col = tid & 127;
            int kk2base = (tid >> 7) * 4;
            #pragma unroll
            for (int q = 0; q < 4; q++) {
                int kk2 = kk2base + q;
                float e = __ldg(&W[(k0 + 2 * kk2)     * FDIM + col]);
                float o = __ldg(&W[(k0 + 2 * kk2 + 1) * FDIM + col]);
                Bs2[kk2][col] = make_float2(e, o);
            }
        }
        __syncthreads();
        #pragma unroll
        for (int kk2 = 0; kk2 < 8; kk2++) {
            const ulonglong2* ap = (const ulonglong2*)&As2[kk2][tm * 8];
            ulonglong2 p0 = ap[0], p1 = ap[1], p2 = ap[2], p3 = ap[3];
            unsigned long long av[8] = {p0.x, p0.y, p1.x, p1.y, p2.x, p2.y, p3.x, p3.y};
            unsigned long long bv[8];
            #pragma unroll
            for (int j = 0; j < 8; j++)
                bv[j] = *(const unsigned long long*)&Bs2[kk2][tn + 16 * j];
            #pragma unroll
            for (int i = 0; i < 8; i++)
                #pragma unroll
                for (int j = 0; j < 8; j++)
                    asm("fma.rn.f32x2 %0, %1, %2, %0;"
                        : "+l"(acc[i][j]) : "l"(av[i]), "l"(bv[j]));
        }
        __syncthreads();
    }

    #pragma unroll
    for (int i = 0; i < 8; i++) {
        int grow = row0 + tm * 8 + i;
        if (grow >= n) break;
        if (halfOut) {
            float s = g_norm_out[grow];
            #pragma unroll
            for (int j = 0; j < 8; j++) {
                float2 p = *(float2*)&acc[i][j];
                float v = p.x + p.y + bb[j];
                v = fmaxf(v, 0.f) * s;          // layers 0/1 always relu
                g_xh[grow * FDIM + tn + 16 * j] = __float2half_rn(v);
            }
        } else {
            #pragma unroll
            for (int j = 0; j < 8; j++) {
                float2 p = *(float2*)&acc[i][j];
                float v = p.x + p.y + bb[j];
                if (relu) v = fmaxf(v, 0.f);
                g_xf[grow * FDIM + tn + 16 * j] = v;
            }
        }
    }
}

// Fused pooling + MLP head (reads g_xf). graph_id sorted -> contiguous ranges.
__global__ void __launch_bounds__(256) k_pool_mlp(const int* __restrict__ gid, int n,
                                                  const float* __restrict__ lin1_W,
                                                  const float* __restrict__ lin1_b,
                                                  const float* __restrict__ lin2_W,
                                                  const float* __restrict__ lin2_b,
                                                  float* __restrict__ out) {
    __shared__ float gs[FDIM];
    __shared__ float hs[FDIM];
    __shared__ int s_lo, s_hi;
    const int g = blockIdx.x;
    const int tid = threadIdx.x;

    if (tid == 0) {
        int lo = 0, hi = n;
        while (lo < hi) { int m = (lo + hi) >> 1; if (__ldg(&gid[m]) < g) lo = m + 1; else hi = m; }
        s_lo = lo;
    } else if (tid == 32) {
        int lo = 0, hi = n;
        while (lo < hi) { int m = (lo + hi) >> 1; if (__ldg(&gid[m]) <= g) lo = m + 1; else hi = m; }
        s_hi = lo;
    }
    __syncthreads();

    const int lo = s_lo, hi = s_hi;
    if (tid < FDIM) {
        float acc = 0.f;
        for (int node = lo; node < hi; node++)
            acc += g_xf[node * FDIM + tid];
        gs[tid] = acc;
    }
    __syncthreads();
    if (tid < FDIM) {
        float acc = __ldg(&lin1_b[tid]);
        #pragma unroll 8
        for (int k = 0; k < FDIM; k++)
            acc += gs[k] * __ldg(&lin1_W[k * FDIM + tid]);
        hs[tid] = fmaxf(acc, 0.f);
    }
    __syncthreads();
    for (int c = tid; c < OUTD; c += blockDim.x) {
        float acc = __ldg(&lin2_b[c]);
        #pragma unroll 8
        for (int k = 0; k < FDIM; k++)
            acc += hs[k] * __ldg(&lin2_W[k * OUTD + c]);
        out[g * OUTD + c] = acc;
    }
}

// ---------------- launch ----------------
extern "C" void kernel_launch(void* const* d_in, const int* in_sizes, int n_in,
                              void* d_out, int out_size) {
    const int*   nid        = (const int*)  d_in[0];
    const int*   z          = (const int*)  d_in[1];
    const int*   src        = (const int*)  d_in[2];
    const int*   dst        = (const int*)  d_in[3];
    const int*   graph_id   = (const int*)  d_in[4];
    const float* init_embed = (const float*)d_in[5];
    const float* z_table    = (const float*)d_in[6];
    const float* W0 = (const float*)d_in[7];
    const float* b0 = (const float*)d_in[8];
    const float* W1 = (const float*)d_in[9];
    const float* b1 = (const float*)d_in[10];
    const float* W2 = (const float*)d_in[11];
    const float* b2 = (const float*)d_in[12];
    const float* lin1_W = (const float*)d_in[13];
    const float* lin1_b = (const float*)d_in[14];
    const float* lin2_W = (const float*)d_in[15];
    const float* lin2_b = (const float*)d_in[16];
    float* out = (float*)d_out;

    const int n = in_sizes[0];       // 50000
    const int E = in_sizes[2];       // 800000
    const int nb = (n + SCAN_B - 1) / SCAN_B;

    // 1) degrees
    k_zero_deg<<<256, 256>>>(2 * n);
    k_deg<<<(E + 511) / 512, 512>>>(src, dst, E, n);

    // 2) norms + CSR row offsets, then fill
    k_scan1<<<nb, SCAN_B>>>(n);
    k_scan3<<<nb, SCAN_B>>>(n, nb);
    k_fill<<<(E + 511) / 512, 512>>>(src, dst, E);

    // 3) node features (half, pre-scaled by norm_out)
    k_features<<<(n * 32 + 255) / 256, 256>>>(nid, z, init_embed, z_table, n);

    // 4) 3 GCN layers: spmm (g_xh -> g_agg), gemm (g_agg -> g_xh / g_xf)
    const int spmm_blocks = (n + 3) / 4;
    const int gemm_blocks = (n + 127) / 128;
    k_spmm<<<spmm_blocks, 128>>>(n);
    k_gemm<<<gemm_blocks, 256>>>(W0, b0, n, 1, 1);
    k_spmm<<<spmm_blocks, 128>>>(n);
    k_gemm<<<gemm_blocks, 256>>>(W1, b1, n, 1, 1);
    k_spmm<<<spmm_blocks, 128>>>(n);
    k_gemm<<<gemm_blocks, 256>>>(W2, b2, n, 0, 0);

    // 5) fused pooling + MLP head
    k_pool_mlp<<<G_CNT, 256>>>(graph_id, n, lin1_W, lin1_b, lin2_W, lin2_b, out);
}

// round 6
// speedup vs baseline: 1.9525x; 1.4792x over previous
#include <cuda_runtime.h>
#include <cuda_fp16.h>
#include <cstdint>

#define N_MAX   50000
#define E_MAX   800000
#define G_CNT   512
#define FDIM    128
#define OUTD    200
#define SCAN_B  1024
#define AP      136                    // smem pitch in halves (conflict-free ldmatrix)
#define GEMM_SMEM (2 * 128 * AP * 2)   // A tile + W tile, bytes

// ---------------- device scratch (static, no allocation) ----------------
__device__ __align__(128) __half g_xh[N_MAX * FDIM];    // half features (SpMM input), pre-scaled by norm_out
__device__ __align__(128) __half g_aggh[N_MAX * FDIM];  // half aggregated (GEMM input)
__device__ __align__(128) float  g_xf[N_MAX * FDIM];    // fp32 final layer output (pool input)
__device__ __align__(128) __half g_Wh[3 * FDIM * FDIM]; // fp16 layer weights
__device__ int   g_deg[2 * N_MAX];
__device__ float g_norm_out[N_MAX];
__device__ float g_norm_in[N_MAX];
__device__ int   g_row_off[N_MAX + 1];
__device__ int   g_cursor[N_MAX];
__device__ int   g_esrc[E_MAX];
__device__ int   g_bsum[64];

// ---------------- setup kernels ----------------

__global__ void k_deg(const int* __restrict__ src, const int* __restrict__ dst, int E, int n) {
    for (int e = blockIdx.x * blockDim.x + threadIdx.x; e < E; e += gridDim.x * blockDim.x) {
        atomicAdd(&g_deg[src[e]], 1);
        atomicAdd(&g_deg[n + dst[e]], 1);
    }
}

__global__ void __launch_bounds__(SCAN_B) k_scan1(int n) {
    __shared__ int wsum[32];
    const int tid = threadIdx.x, lane = tid & 31, wid = tid >> 5;
    const int i = blockIdx.x * SCAN_B + tid;
    int v = 0;
    if (i < n) {
        v = g_deg[n + i];
        g_cursor[i] = 0;
        g_norm_out[i] = rsqrtf(fmaxf((float)g_deg[i], 1.0f));
        g_norm_in[i]  = rsqrtf(fmaxf((float)v, 1.0f));
    }
    int x = v;
    #pragma unroll
    for (int off = 1; off < 32; off <<= 1) {
        int t = __shfl_up_sync(0xffffffffu, x, off);
        if (lane >= off) x += t;
    }
    if (lane == 31) wsum[wid] = x;
    __syncthreads();
    if (wid == 0) {
        int w = wsum[lane];
        #pragma unroll
        for (int off = 1; off < 32; off <<= 1) {
            int t = __shfl_up_sync(0xffffffffu, w, off);
            if (lane >= off) w += t;
        }
        wsum[lane] = w;
    }
    __syncthreads();
    int incl = x + (wid > 0 ? wsum[wid - 1] : 0);
    if (i < n) g_row_off[i + 1] = incl;
    if (tid == SCAN_B - 1) g_bsum[blockIdx.x] = incl;
    if (i == 0) g_row_off[0] = 0;
}

__global__ void __launch_bounds__(SCAN_B) k_scan3(int n, int nb) {
    __shared__ int soff;
    if (threadIdx.x < 32) {
        int l = threadIdx.x;
        int bid = blockIdx.x;
        int v = (l < nb && l < bid) ? g_bsum[l] : 0;
        if (l + 32 < nb && l + 32 < bid) v += g_bsum[l + 32];
        #pragma unroll
        for (int off = 16; off > 0; off >>= 1)
            v += __shfl_down_sync(0xffffffffu, v, off);
        if (l == 0) soff = v;
    }
    __syncthreads();
    int i = blockIdx.x * SCAN_B + threadIdx.x;
    if (i < n) g_row_off[i + 1] += soff;
}

// Scatter edges into CSR; also re-zeroes g_deg for the next call (deg is dead here).
__global__ void k_fill(const int* __restrict__ src, const int* __restrict__ dst, int E, int n2) {
    int t = blockIdx.x * blockDim.x + threadIdx.x;
    if (t < n2) g_deg[t] = 0;
    for (int e = t; e < E; e += gridDim.x * blockDim.x) {
        int d = dst[e];
        int p = g_row_off[d] + atomicAdd(&g_cursor[d], 1);
        g_esrc[p] = src[e];
    }
}

// fp32 -> fp16 weight conversion for the 3 GCN layers
__global__ void k_wconv(const float* __restrict__ W0, const float* __restrict__ W1,
                        const float* __restrict__ W2) {
    int i = blockIdx.x * blockDim.x + threadIdx.x;
    if (i < FDIM * FDIM) {
        g_Wh[i]                   = __float2half_rn(__ldg(&W0[i]));
        g_Wh[FDIM * FDIM + i]     = __float2half_rn(__ldg(&W1[i]));
        g_Wh[2 * FDIM * FDIM + i] = __float2half_rn(__ldg(&W2[i]));
    }
}

// x_h = half( concat(init_embed[nid], z_table[z]) * norm_out[node] )
__global__ void k_features(const int* __restrict__ nid, const int* __restrict__ z,
                           const float* __restrict__ init_embed,
                           const float* __restrict__ z_table, int n) {
    int total = n * 32;
    for (int idx = blockIdx.x * blockDim.x + threadIdx.x; idx < total; idx += gridDim.x * blockDim.x) {
        int node = idx >> 5, q = idx & 31;
        float4 v;
        if (q < 16) v = __ldg(&((const float4*)init_embed)[(long)nid[node] * 16 + q]);
        else        v = __ldg(&((const float4*)z_table)[(long)z[node] * 16 + (q - 16)]);
        float s = g_norm_out[node];
        __half2 h0 = __floats2half2_rn(v.x * s, v.y * s);
        __half2 h1 = __floats2half2_rn(v.z * s, v.w * s);
        uint2 pk;
        pk.x = *(unsigned*)&h0;
        pk.y = *(unsigned*)&h1;
        ((uint2*)g_xh)[node * 32 + q] = pk;
    }
}

// SpMM gather-reduce over half features; fp32 accumulate, half output.
__global__ void __launch_bounds__(128) k_spmm(int n) {
    int warp = blockIdx.x * (blockDim.x >> 5) + (threadIdx.x >> 5);
    int lane = threadIdx.x & 31;
    if (warp >= n) return;
    int e0 = g_row_off[warp], e1 = g_row_off[warp + 1];
    float4 a0 = make_float4(0.f, 0.f, 0.f, 0.f);
    float4 a1 = a0, a2 = a0, a3 = a0;
    const uint2* xh = (const uint2*)g_xh;
    int e = e0;
    for (; e + 3 < e1; e += 4) {
        int s0 = __ldg(&g_esrc[e]);
        int s1 = __ldg(&g_esrc[e + 1]);
        int s2 = __ldg(&g_esrc[e + 2]);
        int s3 = __ldg(&g_esrc[e + 3]);
        uint2 p0 = __ldg(&xh[s0 * 32 + lane]);
        uint2 p1 = __ldg(&xh[s1 * 32 + lane]);
        uint2 p2 = __ldg(&xh[s2 * 32 + lane]);
        uint2 p3 = __ldg(&xh[s3 * 32 + lane]);
        float2 f;
        f = __half22float2(*(__half2*)&p0.x); a0.x += f.x; a0.y += f.y;
        f = __half22float2(*(__half2*)&p0.y); a0.z += f.x; a0.w += f.y;
        f = __half22float2(*(__half2*)&p1.x); a1.x += f.x; a1.y += f.y;
        f = __half22float2(*(__half2*)&p1.y); a1.z += f.x; a1.w += f.y;
        f = __half22float2(*(__half2*)&p2.x); a2.x += f.x; a2.y += f.y;
        f = __half22float2(*(__half2*)&p2.y); a2.z += f.x; a2.w += f.y;
        f = __half22float2(*(__half2*)&p3.x); a3.x += f.x; a3.y += f.y;
        f = __half22float2(*(__half2*)&p3.y); a3.z += f.x; a3.w += f.y;
    }
    for (; e < e1; e++) {
        int s0 = __ldg(&g_esrc[e]);
        uint2 p0 = __ldg(&xh[s0 * 32 + lane]);
        float2 f;
        f = __half22float2(*(__half2*)&p0.x); a0.x += f.x; a0.y += f.y;
        f = __half22float2(*(__half2*)&p0.y); a0.z += f.x; a0.w += f.y;
    }
    float ni = g_norm_in[warp];
    __half2 h0 = __floats2half2_rn((a0.x + a1.x + a2.x + a3.x) * ni,
                                   (a0.y + a1.y + a2.y + a3.y) * ni);
    __half2 h1 = __floats2half2_rn((a0.z + a1.z + a2.z + a3.z) * ni,
                                   (a0.w + a1.w + a2.w + a3.w) * ni);
    uint2 pk;
    pk.x = *(unsigned*)&h0;
    pk.y = *(unsigned*)&h1;
    ((uint2*)g_aggh)[warp * 32 + lane] = pk;
}

// ---------------- HMMA GEMM: out = act(g_aggh @ g_Wh[layer] + b) ----------------
// 128x128 tile per block, 8 warps, mma.sync.m16n8k16 f16*f16 -> f32 accumulate.
// mode 1: relu, *norm_out, half -> g_xh (layers 0/1); mode 0: fp32 -> g_xf (layer 2).
__global__ void __launch_bounds__(256) k_gemm_h(int layer,
                                                const float* __restrict__ bias,
                                                int n, int mode) {
    extern __shared__ __half sh[];
    __half* As = sh;               // [128][AP]
    __half* Ws = sh + 128 * AP;    // [128][AP]
    const int tid = threadIdx.x;
    const int w = tid >> 5, lane = tid & 31;
    const int row0 = blockIdx.x * 128;

    // stage A (guarded) and W into smem: 2 threads per row, 8 x 16B segments each
    {
        const uint4* asrc = (const uint4*)g_aggh;                       // 16 uint4/row
        const uint4* wsrc = (const uint4*)(g_Wh + layer * FDIM * FDIM); // 16 uint4/row
        int r = tid >> 1;
        int s0 = (tid & 1) * 8;
        int grow = row0 + r;
        #pragma unroll
        for (int s = 0; s < 8; s++) {
            uint4 av = make_uint4(0u, 0u, 0u, 0u);
            if (grow < n) av = __ldg(&asrc[grow * 16 + s0 + s]);
            *(uint4*)&As[r * AP + (s0 + s) * 8] = av;
            uint4 wv = __ldg(&wsrc[r * 16 + s0 + s]);
            *(uint4*)&Ws[r * AP + (s0 + s) * 8] = wv;
        }
    }
    __syncthreads();

    float acc[16][4];
    #pragma unroll
    for (int nt = 0; nt < 16; nt++)
        #pragma unroll
        for (int q = 0; q < 4; q++) acc[nt][q] = 0.f;

    #pragma unroll
    for (int kk = 0; kk < 8; kk++) {
        unsigned a0, a1, a2, a3;
        {
            int arow = 16 * w + (lane & 15);
            int acol = kk * 16 + ((lane >> 4) << 3);
            unsigned aaddr = (unsigned)__cvta_generic_to_shared(&As[arow * AP + acol]);
            asm volatile("ldmatrix.sync.aligned.m8n8.x4.shared.b16 {%0,%1,%2,%3}, [%4];"
                         : "=r"(a0), "=r"(a1), "=r"(a2), "=r"(a3) : "r"(aaddr));
        }
        int brow = kk * 16 + (lane & 15);
        unsigned bbase = (unsigned)__cvta_generic_to_shared(&Ws[brow * AP]);
        #pragma unroll
        for (int nt = 0; nt < 16; nt++) {
            unsigned b0, b1;
            asm volatile("ldmatrix.sync.aligned.m8n8.x2.trans.shared.b16 {%0,%1}, [%2];"
                         : "=r"(b0), "=r"(b1) : "r"(bbase + nt * 16u));
            asm volatile("mma.sync.aligned.m16n8k16.row.col.f32.f16.f16.f32 "
                         "{%0,%1,%2,%3}, {%4,%5,%6,%7}, {%8,%9}, {%0,%1,%2,%3};"
                         : "+f"(acc[nt][0]), "+f"(acc[nt][1]), "+f"(acc[nt][2]), "+f"(acc[nt][3])
                         : "r"(a0), "r"(a1), "r"(a2), "r"(a3), "r"(b0), "r"(b1));
        }
    }

    const int rlo = row0 + 16 * w + (lane >> 2);
    const int rhi = rlo + 8;
    const int cbase = (lane & 3) * 2;
    float slo = 1.f, shi = 1.f;
    if (mode) {
        if (rlo < n) slo = g_norm_out[rlo];
        if (rhi < n) shi = g_norm_out[rhi];
    }
    #pragma unroll
    for (int nt = 0; nt < 16; nt++) {
        int c = nt * 8 + cbase;
        float b0v = __ldg(&bias[c]), b1v = __ldg(&bias[c + 1]);
        if (mode) {
            if (rlo < n) {
                __half2 h = __floats2half2_rn(fmaxf(acc[nt][0] + b0v, 0.f) * slo,
                                              fmaxf(acc[nt][1] + b1v, 0.f) * slo);
                *(__half2*)&g_xh[rlo * FDIM + c] = h;
            }
            if (rhi < n) {
                __half2 h = __floats2half2_rn(fmaxf(acc[nt][2] + b0v, 0.f) * shi,
                                              fmaxf(acc[nt][3] + b1v, 0.f) * shi);
                *(__half2*)&g_xh[rhi * FDIM + c] = h;
            }
        } else {
            if (rlo < n)
                *(float2*)&g_xf[rlo * FDIM + c] = make_float2(acc[nt][0] + b0v, acc[nt][1] + b1v);
            if (rhi < n)
                *(float2*)&g_xf[rhi * FDIM + c] = make_float2(acc[nt][2] + b0v, acc[nt][3] + b1v);
        }
    }
}

// Fused pooling + MLP head (reads g_xf). graph_id sorted -> contiguous ranges.
__global__ void __launch_bounds__(256) k_pool_mlp(const int* __restrict__ gid, int n,
                                                  const float* __restrict__ lin1_W,
                                                  const float* __restrict__ lin1_b,
                                                  const float* __restrict__ lin2_W,
                                                  const float* __restrict__ lin2_b,
                                                  float* __restrict__ out) {
    __shared__ float gs[FDIM];
    __shared__ float hs[FDIM];
    __shared__ int s_lo, s_hi;
    const int g = blockIdx.x;
    const int tid = threadIdx.x;

    if (tid == 0) {
        int lo = 0, hi = n;
        while (lo < hi) { int m = (lo + hi) >> 1; if (__ldg(&gid[m]) < g) lo = m + 1; else hi = m; }
        s_lo = lo;
    } else if (tid == 32) {
        int lo = 0, hi = n;
        while (lo < hi) { int m = (lo + hi) >> 1; if (__ldg(&gid[m]) <= g) lo = m + 1; else hi = m; }
        s_hi = lo;
    }
    __syncthreads();

    const int lo = s_lo, hi = s_hi;
    if (tid < FDIM) {
        float acc = 0.f;
        for (int node = lo; node < hi; node++)
            acc += g_xf[node * FDIM + tid];
        gs[tid] = acc;
    }
    __syncthreads();
    if (tid < FDIM) {
        float acc = __ldg(&lin1_b[tid]);
        #pragma unroll 8
        for (int k = 0; k < FDIM; k++)
            acc += gs[k] * __ldg(&lin1_W[k * FDIM + tid]);
        hs[tid] = fmaxf(acc, 0.f);
    }
    __syncthreads();
    for (int c = tid; c < OUTD; c += blockDim.x) {
        float acc = __ldg(&lin2_b[c]);
        #pragma unroll 8
        for (int k = 0; k < FDIM; k++)
            acc += hs[k] * __ldg(&lin2_W[k * OUTD + c]);
        out[g * OUTD + c] = acc;
    }
}

// ---------------- launch ----------------
extern "C" void kernel_launch(void* const* d_in, const int* in_sizes, int n_in,
                              void* d_out, int out_size) {
    const int*   nid        = (const int*)  d_in[0];
    const int*   z          = (const int*)  d_in[1];
    const int*   src        = (const int*)  d_in[2];
    const int*   dst        = (const int*)  d_in[3];
    const int*   graph_id   = (const int*)  d_in[4];
    const float* init_embed = (const float*)d_in[5];
    const float* z_table    = (const float*)d_in[6];
    const float* W0 = (const float*)d_in[7];
    const float* b0 = (const float*)d_in[8];
    const float* W1 = (const float*)d_in[9];
    const float* b1 = (const float*)d_in[10];
    const float* W2 = (const float*)d_in[11];
    const float* b2 = (const float*)d_in[12];
    const float* lin1_W = (const float*)d_in[13];
    const float* lin1_b = (const float*)d_in[14];
    const float* lin2_W = (const float*)d_in[15];
    const float* lin2_b = (const float*)d_in[16];
    float* out = (float*)d_out;

    const int n = in_sizes[0];       // 50000
    const int E = in_sizes[2];       // 800000
    const int nb = (n + SCAN_B - 1) / SCAN_B;

    cudaFuncSetAttribute(k_gemm_h, cudaFuncAttributeMaxDynamicSharedMemorySize, GEMM_SMEM);

    // 0) fp16 weight conversion (independent)
    k_wconv<<<(FDIM * FDIM + 255) / 256, 256>>>(W0, W1, W2);

    // 1) degrees (g_deg zeroed by previous call's k_fill, or zero-init at load)
    k_deg<<<(E + 511) / 512, 512>>>(src, dst, E, n);

    // 2) norms + CSR row offsets, then fill (fill re-zeroes g_deg)
    k_scan1<<<nb, SCAN_B>>>(n);
    k_scan3<<<nb, SCAN_B>>>(n, nb);
    k_fill<<<(E + 511) / 512, 512>>>(src, dst, E, 2 * n);

    // 3) node features (half, pre-scaled by norm_out)
    k_features<<<(n * 32 + 255) / 256, 256>>>(nid, z, init_embed, z_table, n);

    // 4) 3 GCN layers: spmm (g_xh -> g_aggh), hmma gemm (g_aggh -> g_xh / g_xf)
    const int spmm_blocks = (n + 3) / 4;
    const int gemm_blocks = (n + 127) / 128;
    k_spmm<<<spmm_blocks, 128>>>(n);
    k_gemm_h<<<gemm_blocks, 256, GEMM_SMEM>>>(0, b0, n, 1);
    k_spmm<<<spmm_blocks, 128>>>(n);
    k_gemm_h<<<gemm_blocks, 256, GEMM_SMEM>>>(1, b1, n, 1);
    k_spmm<<<spmm_blocks, 128>>>(n);
    k_gemm_h<<<gemm_blocks, 256, GEMM_SMEM>>>(2, b2, n, 0);

    // 5) fused pooling + MLP head
    k_pool_mlp<<<G_CNT, 256>>>(graph_id, n, lin1_W, lin1_b, lin2_W, lin2_b, out);
}

// round 7
// speedup vs baseline: 1.9729x; 1.0104x over previous
#include <cuda_runtime.h>
#include <cuda_fp16.h>
#include <cstdint>

#define N_MAX   50000
#define E_MAX   800000
#define G_CNT   512
#define FDIM    128
#define OUTD    200
#define SCAN_B  1024
#define AP      136                    // smem pitch in halves (conflict-free ldmatrix)
#define GEMM_SMEM (2 * 128 * AP * 2)   // A tile + W tile, bytes

// ---------------- device scratch (static, no allocation) ----------------
__device__ __align__(128) __half g_xh[N_MAX * FDIM];    // half features (SpMM input), pre-scaled by norm_out
__device__ __align__(128) __half g_aggh[N_MAX * FDIM];  // half aggregated (GEMM input)
__device__ __align__(128) float  g_xf[N_MAX * FDIM];    // fp32 final layer output (pool input)
__device__ __align__(128) __half g_Wh[3 * FDIM * FDIM]; // fp16 layer weights
__device__ int   g_deg[2 * N_MAX];
__device__ float g_norm_out[N_MAX];
__device__ float g_norm_in[N_MAX];
__device__ int   g_row_off[N_MAX + 1];
__device__ int   g_cursor[N_MAX];
__device__ int   g_esrc[E_MAX];
__device__ int   g_bsum[64];

// ---------------- setup kernels ----------------

// Degree histogram, 4 edges per iteration (vectorized index loads).
__global__ void k_deg(const int* __restrict__ src, const int* __restrict__ dst, int E, int n) {
    const int4* s4 = (const int4*)src;
    const int4* d4 = (const int4*)dst;
    int e4 = E >> 2;
    for (int i = blockIdx.x * blockDim.x + threadIdx.x; i < e4; i += gridDim.x * blockDim.x) {
        int4 a = __ldg(&s4[i]);
        int4 b = __ldg(&d4[i]);
        atomicAdd(&g_deg[a.x], 1); atomicAdd(&g_deg[a.y], 1);
        atomicAdd(&g_deg[a.z], 1); atomicAdd(&g_deg[a.w], 1);
        atomicAdd(&g_deg[n + b.x], 1); atomicAdd(&g_deg[n + b.y], 1);
        atomicAdd(&g_deg[n + b.z], 1); atomicAdd(&g_deg[n + b.w], 1);
    }
    // tail
    int t = blockIdx.x * blockDim.x + threadIdx.x;
    int base = e4 << 2;
    if (t < E - base) {
        atomicAdd(&g_deg[src[base + t]], 1);
        atomicAdd(&g_deg[n + dst[base + t]], 1);
    }
}

__global__ void __launch_bounds__(SCAN_B) k_scan1(int n) {
    __shared__ int wsum[32];
    const int tid = threadIdx.x, lane = tid & 31, wid = tid >> 5;
    const int i = blockIdx.x * SCAN_B + tid;
    int v = 0;
    if (i < n) {
        v = g_deg[n + i];
        g_cursor[i] = 0;
        g_norm_out[i] = rsqrtf(fmaxf((float)g_deg[i], 1.0f));
        g_norm_in[i]  = rsqrtf(fmaxf((float)v, 1.0f));
    }
    int x = v;
    #pragma unroll
    for (int off = 1; off < 32; off <<= 1) {
        int t = __shfl_up_sync(0xffffffffu, x, off);
        if (lane >= off) x += t;
    }
    if (lane == 31) wsum[wid] = x;
    __syncthreads();
    if (wid == 0) {
        int w = wsum[lane];
        #pragma unroll
        for (int off = 1; off < 32; off <<= 1) {
            int t = __shfl_up_sync(0xffffffffu, w, off);
            if (lane >= off) w += t;
        }
        wsum[lane] = w;
    }
    __syncthreads();
    int incl = x + (wid > 0 ? wsum[wid - 1] : 0);
    if (i < n) g_row_off[i + 1] = incl;
    if (tid == SCAN_B - 1) g_bsum[blockIdx.x] = incl;
    if (i == 0) g_row_off[0] = 0;
}

__global__ void __launch_bounds__(SCAN_B) k_scan3(int n, int nb) {
    __shared__ int soff;
    if (threadIdx.x < 32) {
        int l = threadIdx.x;
        int bid = blockIdx.x;
        int v = (l < nb && l < bid) ? g_bsum[l] : 0;
        if (l + 32 < nb && l + 32 < bid) v += g_bsum[l + 32];
        #pragma unroll
        for (int off = 16; off > 0; off >>= 1)
            v += __shfl_down_sync(0xffffffffu, v, off);
        if (l == 0) soff = v;
    }
    __syncthreads();
    int i = blockIdx.x * SCAN_B + threadIdx.x;
    if (i < n) g_row_off[i + 1] += soff;
}

// Scatter edges into CSR; also re-zeroes g_deg for the next call (deg is dead here).
__global__ void k_fill(const int* __restrict__ src, const int* __restrict__ dst, int E, int n2) {
    int t = blockIdx.x * blockDim.x + threadIdx.x;
    if (t < n2) g_deg[t] = 0;
    for (int e = t; e < E; e += gridDim.x * blockDim.x) {
        int d = dst[e];
        int p = g_row_off[d] + atomicAdd(&g_cursor[d], 1);
        g_esrc[p] = src[e];
    }
}

// fp32 -> fp16 weight conversion for the 3 GCN layers
__global__ void k_wconv(const float* __restrict__ W0, const float* __restrict__ W1,
                        const float* __restrict__ W2) {
    int i = blockIdx.x * blockDim.x + threadIdx.x;
    if (i < FDIM * FDIM) {
        g_Wh[i]                   = __float2half_rn(__ldg(&W0[i]));
        g_Wh[FDIM * FDIM + i]     = __float2half_rn(__ldg(&W1[i]));
        g_Wh[2 * FDIM * FDIM + i] = __float2half_rn(__ldg(&W2[i]));
    }
}

// x_h = half( concat(init_embed[nid], z_table[z]) * norm_out[node] )
__global__ void k_features(const int* __restrict__ nid, const int* __restrict__ z,
                           const float* __restrict__ init_embed,
                           const float* __restrict__ z_table, int n) {
    int total = n * 32;
    for (int idx = blockIdx.x * blockDim.x + threadIdx.x; idx < total; idx += gridDim.x * blockDim.x) {
        int node = idx >> 5, q = idx & 31;
        float4 v;
        if (q < 16) v = __ldg(&((const float4*)init_embed)[(long)nid[node] * 16 + q]);
        else        v = __ldg(&((const float4*)z_table)[(long)z[node] * 16 + (q - 16)]);
        float s = g_norm_out[node];
        __half2 h0 = __floats2half2_rn(v.x * s, v.y * s);
        __half2 h1 = __floats2half2_rn(v.z * s, v.w * s);
        uint2 pk;
        pk.x = *(unsigned*)&h0;
        pk.y = *(unsigned*)&h1;
        ((uint2*)g_xh)[node * 32 + q] = pk;
    }
}

// SpMM gather-reduce: HALF-WARP per dst row. 16 lanes x uint4 (8 halves) = 256B row.
// 2 rows per warp, edge loop unrolled x4 -> 8 outstanding row-gathers per warp.
// fp32 accumulate, half output.
__global__ void __launch_bounds__(256) k_spmm(int n) {
    int row = blockIdx.x * 16 + (threadIdx.x >> 4);
    int hl  = threadIdx.x & 15;
    if (row >= n) return;
    int e0 = g_row_off[row], e1 = g_row_off[row + 1];
    const uint4* xh = (const uint4*)g_xh;   // 16 uint4 per row
    float a0 = 0.f, a1 = 0.f, a2 = 0.f, a3 = 0.f, a4 = 0.f, a5 = 0.f, a6 = 0.f, a7 = 0.f;
    int e = e0;
    for (; e + 3 < e1; e += 4) {
        int s0 = __ldg(&g_esrc[e]);
        int s1 = __ldg(&g_esrc[e + 1]);
        int s2 = __ldg(&g_esrc[e + 2]);
        int s3 = __ldg(&g_esrc[e + 3]);
        uint4 p0 = __ldg(&xh[s0 * 16 + hl]);
        uint4 p1 = __ldg(&xh[s1 * 16 + hl]);
        uint4 p2 = __ldg(&xh[s2 * 16 + hl]);
        uint4 p3 = __ldg(&xh[s3 * 16 + hl]);
        float2 f;
        f = __half22float2(*(__half2*)&p0.x); a0 += f.x; a1 += f.y;
        f = __half22float2(*(__half2*)&p0.y); a2 += f.x; a3 += f.y;
        f = __half22float2(*(__half2*)&p0.z); a4 += f.x; a5 += f.y;
        f = __half22float2(*(__half2*)&p0.w); a6 += f.x; a7 += f.y;
        f = __half22float2(*(__half2*)&p1.x); a0 += f.x; a1 += f.y;
        f = __half22float2(*(__half2*)&p1.y); a2 += f.x; a3 += f.y;
        f = __half22float2(*(__half2*)&p1.z); a4 += f.x; a5 += f.y;
        f = __half22float2(*(__half2*)&p1.w); a6 += f.x; a7 += f.y;
        f = __half22float2(*(__half2*)&p2.x); a0 += f.x; a1 += f.y;
        f = __half22float2(*(__half2*)&p2.y); a2 += f.x; a3 += f.y;
        f = __half22float2(*(__half2*)&p2.z); a4 += f.x; a5 += f.y;
        f = __half22float2(*(__half2*)&p2.w); a6 += f.x; a7 += f.y;
        f = __half22float2(*(__half2*)&p3.x); a0 += f.x; a1 += f.y;
        f = __half22float2(*(__half2*)&p3.y); a2 += f.x; a3 += f.y;
        f = __half22float2(*(__half2*)&p3.z); a4 += f.x; a5 += f.y;
        f = __half22float2(*(__half2*)&p3.w); a6 += f.x; a7 += f.y;
    }
    for (; e < e1; e++) {
        int s0 = __ldg(&g_esrc[e]);
        uint4 p0 = __ldg(&xh[s0 * 16 + hl]);
        float2 f;
        f = __half22float2(*(__half2*)&p0.x); a0 += f.x; a1 += f.y;
        f = __half22float2(*(__half2*)&p0.y); a2 += f.x; a3 += f.y;
        f = __half22float2(*(__half2*)&p0.z); a4 += f.x; a5 += f.y;
        f = __half22float2(*(__half2*)&p0.w); a6 += f.x; a7 += f.y;
    }
    float ni = g_norm_in[row];
    __half2 h0 = __floats2half2_rn(a0 * ni, a1 * ni);
    __half2 h1 = __floats2half2_rn(a2 * ni, a3 * ni);
    __half2 h2 = __floats2half2_rn(a4 * ni, a5 * ni);
    __half2 h3 = __floats2half2_rn(a6 * ni, a7 * ni);
    uint4 pk;
    pk.x = *(unsigned*)&h0;
    pk.y = *(unsigned*)&h1;
    pk.z = *(unsigned*)&h2;
    pk.w = *(unsigned*)&h3;
    ((uint4*)g_aggh)[row * 16 + hl] = pk;
}

// ---------------- HMMA GEMM: out = act(g_aggh @ g_Wh[layer] + b) ----------------
// 128x128 tile per block, 8 warps, mma.sync.m16n8k16 f16*f16 -> f32 accumulate.
// mode 1: relu, *norm_out, half -> g_xh (layers 0/1); mode 0: fp32 -> g_xf (layer 2).
__global__ void __launch_bounds__(256) k_gemm_h(int layer,
                                                const float* __restrict__ bias,
                                                int n, int mode) {
    extern __shared__ __half sh[];
    __half* As = sh;               // [128][AP]
    __half* Ws = sh + 128 * AP;    // [128][AP]
    const int tid = threadIdx.x;
    const int w = tid >> 5, lane = tid & 31;
    const int row0 = blockIdx.x * 128;

    {
        const uint4* asrc = (const uint4*)g_aggh;                       // 16 uint4/row
        const uint4* wsrc = (const uint4*)(g_Wh + layer * FDIM * FDIM); // 16 uint4/row
        int r = tid >> 1;
        int s0 = (tid & 1) * 8;
        int grow = row0 + r;
        #pragma unroll
        for (int s = 0; s < 8; s++) {
            uint4 av = make_uint4(0u, 0u, 0u, 0u);
            if (grow < n) av = __ldg(&asrc[grow * 16 + s0 + s]);
            *(uint4*)&As[r * AP + (s0 + s) * 8] = av;
            uint4 wv = __ldg(&wsrc[r * 16 + s0 + s]);
            *(uint4*)&Ws[r * AP + (s0 + s) * 8] = wv;
        }
    }
    __syncthreads();

    float acc[16][4];
    #pragma unroll
    for (int nt = 0; nt < 16; nt++)
        #pragma unroll
        for (int q = 0; q < 4; q++) acc[nt][q] = 0.f;

    #pragma unroll
    for (int kk = 0; kk < 8; kk++) {
        unsigned a0, a1, a2, a3;
        {
            int arow = 16 * w + (lane & 15);
            int acol = kk * 16 + ((lane >> 4) << 3);
            unsigned aaddr = (unsigned)__cvta_generic_to_shared(&As[arow * AP + acol]);
            asm volatile("ldmatrix.sync.aligned.m8n8.x4.shared.b16 {%0,%1,%2,%3}, [%4];"
                         : "=r"(a0), "=r"(a1), "=r"(a2), "=r"(a3) : "r"(aaddr));
        }
        int brow = kk * 16 + (lane & 15);
        unsigned bbase = (unsigned)__cvta_generic_to_shared(&Ws[brow * AP]);
        #pragma unroll
        for (int nt = 0; nt < 16; nt++) {
            unsigned b0, b1;
            asm volatile("ldmatrix.sync.aligned.m8n8.x2.trans.shared.b16 {%0,%1}, [%2];"
                         : "=r"(b0), "=r"(b1) : "r"(bbase + nt * 16u));
            asm volatile("mma.sync.aligned.m16n8k16.row.col.f32.f16.f16.f32 "
                         "{%0,%1,%2,%3}, {%4,%5,%6,%7}, {%8,%9}, {%0,%1,%2,%3};"
                         : "+f"(acc[nt][0]), "+f"(acc[nt][1]), "+f"(acc[nt][2]), "+f"(acc[nt][3])
                         : "r"(a0), "r"(a1), "r"(a2), "r"(a3), "r"(b0), "r"(b1));
        }
    }

    const int rlo = row0 + 16 * w + (lane >> 2);
    const int rhi = rlo + 8;
    const int cbase = (lane & 3) * 2;
    float slo = 1.f, shi = 1.f;
    if (mode) {
        if (rlo < n) slo = g_norm_out[rlo];
        if (rhi < n) shi = g_norm_out[rhi];
    }
    #pragma unroll
    for (int nt = 0; nt < 16; nt++) {
        int c = nt * 8 + cbase;
        float b0v = __ldg(&bias[c]), b1v = __ldg(&bias[c + 1]);
        if (mode) {
            if (rlo < n) {
                __half2 h = __floats2half2_rn(fmaxf(acc[nt][0] + b0v, 0.f) * slo,
                                              fmaxf(acc[nt][1] + b1v, 0.f) * slo);
                *(__half2*)&g_xh[rlo * FDIM + c] = h;
            }
            if (rhi < n) {
                __half2 h = __floats2half2_rn(fmaxf(acc[nt][2] + b0v, 0.f) * shi,
                                              fmaxf(acc[nt][3] + b1v, 0.f) * shi);
                *(__half2*)&g_xh[rhi * FDIM + c] = h;
            }
        } else {
            if (rlo < n)
                *(float2*)&g_xf[rlo * FDIM + c] = make_float2(acc[nt][0] + b0v, acc[nt][1] + b1v);
            if (rhi < n)
                *(float2*)&g_xf[rhi * FDIM + c] = make_float2(acc[nt][2] + b0v, acc[nt][3] + b1v);
        }
    }
}

// Fused pooling + MLP head (reads g_xf). graph_id sorted -> contiguous ranges.
__global__ void __launch_bounds__(256) k_pool_mlp(const int* __restrict__ gid, int n,
                                                  const float* __restrict__ lin1_W,
                                                  const float* __restrict__ lin1_b,
                                                  const float* __restrict__ lin2_W,
                                                  const float* __restrict__ lin2_b,
                                                  float* __restrict__ out) {
    __shared__ float gs[FDIM];
    __shared__ float hs[FDIM];
    __shared__ int s_lo, s_hi;
    const int g = blockIdx.x;
    const int tid = threadIdx.x;

    if (tid == 0) {
        int lo = 0, hi = n;
        while (lo < hi) { int m = (lo + hi) >> 1; if (__ldg(&gid[m]) < g) lo = m + 1; else hi = m; }
        s_lo = lo;
    } else if (tid == 32) {
        int lo = 0, hi = n;
        while (lo < hi) { int m = (lo + hi) >> 1; if (__ldg(&gid[m]) <= g) lo = m + 1; else hi = m; }
        s_hi = lo;
    }
    __syncthreads();

    const int lo = s_lo, hi = s_hi;
    if (tid < FDIM) {
        float acc = 0.f;
        for (int node = lo; node < hi; node++)
            acc += g_xf[node * FDIM + tid];
        gs[tid] = acc;
    }
    __syncthreads();
    if (tid < FDIM) {
        float acc = __ldg(&lin1_b[tid]);
        #pragma unroll 8
        for (int k = 0; k < FDIM; k++)
            acc += gs[k] * __ldg(&lin1_W[k * FDIM + tid]);
        hs[tid] = fmaxf(acc, 0.f);
    }
    __syncthreads();
    for (int c = tid; c < OUTD; c += blockDim.x) {
        float acc = __ldg(&lin2_b[c]);
        #pragma unroll 8
        for (int k = 0; k < FDIM; k++)
            acc += hs[k] * __ldg(&lin2_W[k * OUTD + c]);
        out[g * OUTD + c] = acc;
    }
}

// ---------------- launch ----------------
extern "C" void kernel_launch(void* const* d_in, const int* in_sizes, int n_in,
                              void* d_out, int out_size) {
    const int*   nid        = (const int*)  d_in[0];
    const int*   z          = (const int*)  d_in[1];
    const int*   src        = (const int*)  d_in[2];
    const int*   dst        = (const int*)  d_in[3];
    const int*   graph_id   = (const int*)  d_in[4];
    const float* init_embed = (const float*)d_in[5];
    const float* z_table    = (const float*)d_in[6];
    const float* W0 = (const float*)d_in[7];
    const float* b0 = (const float*)d_in[8];
    const float* W1 = (const float*)d_in[9];
    const float* b1 = (const float*)d_in[10];
    const float* W2 = (const float*)d_in[11];
    const float* b2 = (const float*)d_in[12];
    const float* lin1_W = (const float*)d_in[13];
    const float* lin1_b = (const float*)d_in[14];
    const float* lin2_W = (const float*)d_in[15];
    const float* lin2_b = (const float*)d_in[16];
    float* out = (float*)d_out;

    const int n = in_sizes[0];       // 50000
    const int E = in_sizes[2];       // 800000
    const int nb = (n + SCAN_B - 1) / SCAN_B;

    cudaFuncSetAttribute(k_gemm_h, cudaFuncAttributeMaxDynamicSharedMemorySize, GEMM_SMEM);

    // 0) fp16 weight conversion (independent)
    k_wconv<<<(FDIM * FDIM + 255) / 256, 256>>>(W0, W1, W2);

    // 1) degrees (g_deg zeroed by previous call's k_fill, or zero-init at load)
    k_deg<<<((E >> 2) + 255) / 256, 256>>>(src, dst, E, n);

    // 2) norms + CSR row offsets, then fill (fill re-zeroes g_deg)
    k_scan1<<<nb, SCAN_B>>>(n);
    k_scan3<<<nb, SCAN_B>>>(n, nb);
    k_fill<<<(E + 511) / 512, 512>>>(src, dst, E, 2 * n);

    // 3) node features (half, pre-scaled by norm_out)
    k_features<<<(n * 32 + 255) / 256, 256>>>(nid, z, init_embed, z_table, n);

    // 4) 3 GCN layers: spmm (g_xh -> g_aggh), hmma gemm (g_aggh -> g_xh / g_xf)
    const int spmm_blocks = (n + 15) / 16;
    const int gemm_blocks = (n + 127) / 128;
    k_spmm<<<spmm_blocks, 256>>>(n);
    k_gemm_h<<<gemm_blocks, 256, GEMM_SMEM>>>(0, b0, n, 1);
    k_spmm<<<spmm_blocks, 256>>>(n);
    k_gemm_h<<<gemm_blocks, 256, GEMM_SMEM>>>(1, b1, n, 1);
    k_spmm<<<spmm_blocks, 256>>>(n);
    k_gemm_h<<<gemm_blocks, 256, GEMM_SMEM>>>(2, b2, n, 0);

    // 5) fused pooling + MLP head
    k_pool_mlp<<<G_CNT, 256>>>(graph_id, n, lin1_W, lin1_b, lin2_W, lin2_b, out);
}

// round 8
// speedup vs baseline: 2.1889x; 1.1094x over previous
#include <cuda_runtime.h>
#include <cuda_fp16.h>
#include <cstdint>

#define N_MAX   50000
#define E_MAX   800000
#define G_CNT   512
#define FDIM    128
#define OUTD    200
#define SCAN_B  1024
#define AP      136                    // smem pitch in halves (conflict-free ldmatrix)
#define GEMM_SMEM (2 * 128 * AP * 2)   // A tile + W tile, bytes
#define WCONV_BLOCKS 64                // 64*256 = 16384 = FDIM*FDIM
#define FILL_BLOCKS  784               // 784*256 = 200704 >= 2n and >= E/4

// ---------------- device scratch (static, no allocation) ----------------
__device__ __align__(128) __half g_xh[N_MAX * FDIM];    // half features; also final-layer output for pooling
__device__ __align__(128) __half g_aggh[N_MAX * FDIM];  // half aggregated (GEMM input)
__device__ __align__(128) __half g_Wh[3 * FDIM * FDIM]; // fp16 layer weights
__device__ int   g_deg[2 * N_MAX];
__device__ float g_norm_out[N_MAX];
__device__ float g_norm_in[N_MAX];
__device__ int   g_row_off[N_MAX + 1];
__device__ int   g_cursor[N_MAX];
__device__ int   g_esrc[E_MAX];
__device__ int   g_bsum[64];
__device__ unsigned g_count = 0;            // grid-barrier arrivals
__device__ volatile unsigned g_gen = 0;     // grid-barrier generation (monotonic across replays)

// ---------------- k_prep: fp16 weight conversion + degree histogram ----------------
__global__ void k_prep(const float* __restrict__ W0, const float* __restrict__ W1,
                       const float* __restrict__ W2,
                       const int* __restrict__ src, const int* __restrict__ dst,
                       int E, int n) {
    if (blockIdx.x < WCONV_BLOCKS) {
        int i = blockIdx.x * 256 + threadIdx.x;   // exactly FDIM*FDIM threads
        g_Wh[i]                   = __float2half_rn(__ldg(&W0[i]));
        g_Wh[FDIM * FDIM + i]     = __float2half_rn(__ldg(&W1[i]));
        g_Wh[2 * FDIM * FDIM + i] = __float2half_rn(__ldg(&W2[i]));
    } else {
        const int4* s4 = (const int4*)src;
        const int4* d4 = (const int4*)dst;
        int e4 = E >> 2;
        int nb = gridDim.x - WCONV_BLOCKS;
        int t = (blockIdx.x - WCONV_BLOCKS) * 256 + threadIdx.x;
        for (int i = t; i < e4; i += nb * 256) {
            int4 a = __ldg(&s4[i]);
            int4 b = __ldg(&d4[i]);
            atomicAdd(&g_deg[a.x], 1); atomicAdd(&g_deg[a.y], 1);
            atomicAdd(&g_deg[a.z], 1); atomicAdd(&g_deg[a.w], 1);
            atomicAdd(&g_deg[n + b.x], 1); atomicAdd(&g_deg[n + b.y], 1);
            atomicAdd(&g_deg[n + b.z], 1); atomicAdd(&g_deg[n + b.w], 1);
        }
        int base = e4 << 2;
        if (t < E - base) {
            atomicAdd(&g_deg[src[base + t]], 1);
            atomicAdd(&g_deg[n + dst[base + t]], 1);
        }
    }
}

// ---------------- k_scan: fused two-phase scan with software grid barrier ----------------
// 49 blocks (<=148 SMs) are guaranteed co-resident, so a spin barrier is safe.
__global__ void __launch_bounds__(SCAN_B) k_scan(int n, int nb) {
    __shared__ int wsum[32];
    const int tid = threadIdx.x, lane = tid & 31, wid = tid >> 5;
    const int i = blockIdx.x * SCAN_B + tid;

    // ---- phase A: block-local inclusive scan of deg_in, norms, cursor zero ----
    int v = 0;
    if (i < n) {
        v = g_deg[n + i];
        g_cursor[i] = 0;
        g_norm_out[i] = rsqrtf(fmaxf((float)g_deg[i], 1.0f));
        g_norm_in[i]  = rsqrtf(fmaxf((float)v, 1.0f));
    }
    int x = v;
    #pragma unroll
    for (int off = 1; off < 32; off <<= 1) {
        int t = __shfl_up_sync(0xffffffffu, x, off);
        if (lane >= off) x += t;
    }
    if (lane == 31) wsum[wid] = x;
    __syncthreads();
    if (wid == 0) {
        int w = wsum[lane];
        #pragma unroll
        for (int off = 1; off < 32; off <<= 1) {
            int t = __shfl_up_sync(0xffffffffu, w, off);
            if (lane >= off) w += t;
        }
        wsum[lane] = w;
    }
    __syncthreads();
    int incl = x + (wid > 0 ? wsum[wid - 1] : 0);
    if (i < n) g_row_off[i + 1] = incl;
    if (tid == SCAN_B - 1) g_bsum[blockIdx.x] = incl;
    if (i == 0) g_row_off[0] = 0;

    // ---- grid barrier (generation counter; deterministic across replays) ----
    __syncthreads();
    __threadfence();
    if (tid == 0) {
        unsigned gen = g_gen;
        if (atomicAdd(&g_count, 1u) == gridDim.x - 1) {
            g_count = 0;
            __threadfence();
            g_gen = gen + 1;
        } else {
            while (g_gen == gen) { }
        }
    }
    __syncthreads();
    __threadfence();

    // ---- phase B: add exclusive prefix of block sums ----
    __shared__ int soff;
    if (tid < 32) {
        int l = tid;
        int bid = blockIdx.x;
        int s = (l < nb && l < bid) ? g_bsum[l] : 0;
        if (l + 32 < nb && l + 32 < bid) s += g_bsum[l + 32];
        #pragma unroll
        for (int off = 16; off > 0; off >>= 1)
            s += __shfl_down_sync(0xffffffffu, s, off);
        if (l == 0) soff = s;
    }
    __syncthreads();
    if (i < n) g_row_off[i + 1] += soff;
}

// ---------------- k_build: CSR fill (vectorized) + node features, overlapped ----------------
__global__ void k_build(const int* __restrict__ src, const int* __restrict__ dst,
                        int E, int n2,
                        const int* __restrict__ nid, const int* __restrict__ z,
                        const float* __restrict__ init_embed,
                        const float* __restrict__ z_table, int n) {
    if (blockIdx.x < FILL_BLOCKS) {
        int t = blockIdx.x * 256 + threadIdx.x;
        if (t < n2) g_deg[t] = 0;                 // deg is dead; re-zero for next call
        const int4* s4 = (const int4*)src;
        const int4* d4 = (const int4*)dst;
        int e4 = E >> 2;
        for (int i = t; i < e4; i += FILL_BLOCKS * 256) {
            int4 a = __ldg(&s4[i]);
            int4 b = __ldg(&d4[i]);
            g_esrc[g_row_off[b.x] + atomicAdd(&g_cursor[b.x], 1)] = a.x;
            g_esrc[g_row_off[b.y] + atomicAdd(&g_cursor[b.y], 1)] = a.y;
            g_esrc[g_row_off[b.z] + atomicAdd(&g_cursor[b.z], 1)] = a.z;
            g_esrc[g_row_off[b.w] + atomicAdd(&g_cursor[b.w], 1)] = a.w;
        }
        int base = e4 << 2;
        if (t < E - base) {
            int d = dst[base + t];
            g_esrc[g_row_off[d] + atomicAdd(&g_cursor[d], 1)] = src[base + t];
        }
    } else {
        // features: x_h = half(concat(init_embed[nid], z_table[z]) * norm_out[node])
        int total = n * 32;
        int nb = gridDim.x - FILL_BLOCKS;
        for (int idx = (blockIdx.x - FILL_BLOCKS) * 256 + threadIdx.x; idx < total;
             idx += nb * 256) {
            int node = idx >> 5, q = idx & 31;
            float4 v;
            if (q < 16) v = __ldg(&((const float4*)init_embed)[(long)nid[node] * 16 + q]);
            else        v = __ldg(&((const float4*)z_table)[(long)z[node] * 16 + (q - 16)]);
            float s = g_norm_out[node];
            __half2 h0 = __floats2half2_rn(v.x * s, v.y * s);
            __half2 h1 = __floats2half2_rn(v.z * s, v.w * s);
            uint2 pk;
            pk.x = *(unsigned*)&h0;
            pk.y = *(unsigned*)&h1;
            ((uint2*)g_xh)[node * 32 + q] = pk;
        }
    }
}

// ---------------- SpMM gather-reduce: half-warp per dst row ----------------
__global__ void __launch_bounds__(256) k_spmm(int n) {
    int row = blockIdx.x * 16 + (threadIdx.x >> 4);
    int hl  = threadIdx.x & 15;
    if (row >= n) return;
    int e0 = g_row_off[row], e1 = g_row_off[row + 1];
    const uint4* xh = (const uint4*)g_xh;   // 16 uint4 per row
    float a0 = 0.f, a1 = 0.f, a2 = 0.f, a3 = 0.f, a4 = 0.f, a5 = 0.f, a6 = 0.f, a7 = 0.f;
    int e = e0;
    for (; e + 3 < e1; e += 4) {
        int s0 = __ldg(&g_esrc[e]);
        int s1 = __ldg(&g_esrc[e + 1]);
        int s2 = __ldg(&g_esrc[e + 2]);
        int s3 = __ldg(&g_esrc[e + 3]);
        uint4 p0 = __ldg(&xh[s0 * 16 + hl]);
        uint4 p1 = __ldg(&xh[s1 * 16 + hl]);
        uint4 p2 = __ldg(&xh[s2 * 16 + hl]);
        uint4 p3 = __ldg(&xh[s3 * 16 + hl]);
        float2 f;
        f = __half22float2(*(__half2*)&p0.x); a0 += f.x; a1 += f.y;
        f = __half22float2(*(__half2*)&p0.y); a2 += f.x; a3 += f.y;
        f = __half22float2(*(__half2*)&p0.z); a4 += f.x; a5 += f.y;
        f = __half22float2(*(__half2*)&p0.w); a6 += f.x; a7 += f.y;
        f = __half22float2(*(__half2*)&p1.x); a0 += f.x; a1 += f.y;
        f = __half22float2(*(__half2*)&p1.y); a2 += f.x; a3 += f.y;
        f = __half22float2(*(__half2*)&p1.z); a4 += f.x; a5 += f.y;
        f = __half22float2(*(__half2*)&p1.w); a6 += f.x; a7 += f.y;
        f = __half22float2(*(__half2*)&p2.x); a0 += f.x; a1 += f.y;
        f = __half22float2(*(__half2*)&p2.y); a2 += f.x; a3 += f.y;
        f = __half22float2(*(__half2*)&p2.z); a4 += f.x; a5 += f.y;
        f = __half22float2(*(__half2*)&p2.w); a6 += f.x; a7 += f.y;
        f = __half22float2(*(__half2*)&p3.x); a0 += f.x; a1 += f.y;
        f = __half22float2(*(__half2*)&p3.y); a2 += f.x; a3 += f.y;
        f = __half22float2(*(__half2*)&p3.z); a4 += f.x; a5 += f.y;
        f = __half22float2(*(__half2*)&p3.w); a6 += f.x; a7 += f.y;
    }
    for (; e < e1; e++) {
        int s0 = __ldg(&g_esrc[e]);
        uint4 p0 = __ldg(&xh[s0 * 16 + hl]);
        float2 f;
        f = __half22float2(*(__half2*)&p0.x); a0 += f.x; a1 += f.y;
        f = __half22float2(*(__half2*)&p0.y); a2 += f.x; a3 += f.y;
        f = __half22float2(*(__half2*)&p0.z); a4 += f.x; a5 += f.y;
        f = __half22float2(*(__half2*)&p0.w); a6 += f.x; a7 += f.y;
    }
    float ni = g_norm_in[row];
    __half2 h0 = __floats2half2_rn(a0 * ni, a1 * ni);
    __half2 h1 = __floats2half2_rn(a2 * ni, a3 * ni);
    __half2 h2 = __floats2half2_rn(a4 * ni, a5 * ni);
    __half2 h3 = __floats2half2_rn(a6 * ni, a7 * ni);
    uint4 pk;
    pk.x = *(unsigned*)&h0;
    pk.y = *(unsigned*)&h1;
    pk.z = *(unsigned*)&h2;
    pk.w = *(unsigned*)&h3;
    ((uint4*)g_aggh)[row * 16 + hl] = pk;
}

// ---------------- HMMA GEMM: out = act(g_aggh @ g_Wh[layer] + b) ----------------
// mode 1: relu * norm_out (layers 0/1); mode 0: bias only (layer 2). Both write half to g_xh.
__global__ void __launch_bounds__(256) k_gemm_h(int layer,
                                                const float* __restrict__ bias,
                                                int n, int mode) {
    extern __shared__ __half sh[];
    __half* As = sh;               // [128][AP]
    __half* Ws = sh + 128 * AP;    // [128][AP]
    const int tid = threadIdx.x;
    const int w = tid >> 5, lane = tid & 31;
    const int row0 = blockIdx.x * 128;

    {
        const uint4* asrc = (const uint4*)g_aggh;
        const uint4* wsrc = (const uint4*)(g_Wh + layer * FDIM * FDIM);
        int r = tid >> 1;
        int s0 = (tid & 1) * 8;
        int grow = row0 + r;
        #pragma unroll
        for (int s = 0; s < 8; s++) {
            uint4 av = make_uint4(0u, 0u, 0u, 0u);
            if (grow < n) av = __ldg(&asrc[grow * 16 + s0 + s]);
            *(uint4*)&As[r * AP + (s0 + s) * 8] = av;
            uint4 wv = __ldg(&wsrc[r * 16 + s0 + s]);
            *(uint4*)&Ws[r * AP + (s0 + s) * 8] = wv;
        }
    }
    __syncthreads();

    float acc[16][4];
    #pragma unroll
    for (int nt = 0; nt < 16; nt++)
        #pragma unroll
        for (int q = 0; q < 4; q++) acc[nt][q] = 0.f;

    #pragma unroll
    for (int kk = 0; kk < 8; kk++) {
        unsigned a0, a1, a2, a3;
        {
            int arow = 16 * w + (lane & 15);
            int acol = kk * 16 + ((lane >> 4) << 3);
            unsigned aaddr = (unsigned)__cvta_generic_to_shared(&As[arow * AP + acol]);
            asm volatile("ldmatrix.sync.aligned.m8n8.x4.shared.b16 {%0,%1,%2,%3}, [%4];"
                         : "=r"(a0), "=r"(a1), "=r"(a2), "=r"(a3) : "r"(aaddr));
        }
        int brow = kk * 16 + (lane & 15);
        unsigned bbase = (unsigned)__cvta_generic_to_shared(&Ws[brow * AP]);
        #pragma unroll
        for (int nt = 0; nt < 16; nt++) {
            unsigned b0, b1;
            asm volatile("ldmatrix.sync.aligned.m8n8.x2.trans.shared.b16 {%0,%1}, [%2];"
                         : "=r"(b0), "=r"(b1) : "r"(bbase + nt * 16u));
            asm volatile("mma.sync.aligned.m16n8k16.row.col.f32.f16.f16.f32 "
                         "{%0,%1,%2,%3}, {%4,%5,%6,%7}, {%8,%9}, {%0,%1,%2,%3};"
                         : "+f"(acc[nt][0]), "+f"(acc[nt][1]), "+f"(acc[nt][2]), "+f"(acc[nt][3])
                         : "r"(a0), "r"(a1), "r"(a2), "r"(a3), "r"(b0), "r"(b1));
        }
    }

    const int rlo = row0 + 16 * w + (lane >> 2);
    const int rhi = rlo + 8;
    const int cbase = (lane & 3) * 2;
    float slo = 1.f, shi = 1.f;
    if (mode) {
        if (rlo < n) slo = g_norm_out[rlo];
        if (rhi < n) shi = g_norm_out[rhi];
    }
    #pragma unroll
    for (int nt = 0; nt < 16; nt++) {
        int c = nt * 8 + cbase;
        float b0v = __ldg(&bias[c]), b1v = __ldg(&bias[c + 1]);
        if (rlo < n) {
            float v0 = acc[nt][0] + b0v, v1 = acc[nt][1] + b1v;
            if (mode) { v0 = fmaxf(v0, 0.f) * slo; v1 = fmaxf(v1, 0.f) * slo; }
            __half2 h = __floats2half2_rn(v0, v1);
            *(__half2*)&g_xh[rlo * FDIM + c] = h;
        }
        if (rhi < n) {
            float v2 = acc[nt][2] + b0v, v3 = acc[nt][3] + b1v;
            if (mode) { v2 = fmaxf(v2, 0.f) * shi; v3 = fmaxf(v3, 0.f) * shi; }
            __half2 h = __floats2half2_rn(v2, v3);
            *(__half2*)&g_xh[rhi * FDIM + c] = h;
        }
    }
}

// ---------------- fused pooling + MLP head (reads g_xh half, fp32 accumulate) ----------------
__global__ void __launch_bounds__(256) k_pool_mlp(const int* __restrict__ gid, int n,
                                                  const float* __restrict__ lin1_W,
                                                  const float* __restrict__ lin1_b,
                                                  const float* __restrict__ lin2_W,
                                                  const float* __restrict__ lin2_b,
                                                  float* __restrict__ out) {
    __shared__ float gs[FDIM];
    __shared__ float hs[FDIM];
    __shared__ int s_lo, s_hi;
    const int g = blockIdx.x;
    const int tid = threadIdx.x;

    if (tid == 0) {
        int lo = 0, hi = n;
        while (lo < hi) { int m = (lo + hi) >> 1; if (__ldg(&gid[m]) < g) lo = m + 1; else hi = m; }
        s_lo = lo;
    } else if (tid == 32) {
        int lo = 0, hi = n;
        while (lo < hi) { int m = (lo + hi) >> 1; if (__ldg(&gid[m]) <= g) lo = m + 1; else hi = m; }
        s_hi = lo;
    }
    __syncthreads();

    const int lo = s_lo, hi = s_hi;
    if (tid < 64) {     // thread handles cols 2*tid, 2*tid+1 via half2
        float acc0 = 0.f, acc1 = 0.f;
        const __half2* xh2 = (const __half2*)g_xh;
        for (int node = lo; node < hi; node++) {
            float2 f = __half22float2(xh2[node * 64 + tid]);
            acc0 += f.x; acc1 += f.y;
        }
        gs[2 * tid] = acc0;
        gs[2 * tid + 1] = acc1;
    }
    __syncthreads();
    if (tid < FDIM) {
        float acc = __ldg(&lin1_b[tid]);
        #pragma unroll 8
        for (int k = 0; k < FDIM; k++)
            acc += gs[k] * __ldg(&lin1_W[k * FDIM + tid]);
        hs[tid] = fmaxf(acc, 0.f);
    }
    __syncthreads();
    for (int c = tid; c < OUTD; c += blockDim.x) {
        float acc = __ldg(&lin2_b[c]);
        #pragma unroll 8
        for (int k = 0; k < FDIM; k++)
            acc += hs[k] * __ldg(&lin2_W[k * OUTD + c]);
        out[g * OUTD + c] = acc;
    }
}

// ---------------- launch ----------------
extern "C" void kernel_launch(void* const* d_in, const int* in_sizes, int n_in,
                              void* d_out, int out_size) {
    const int*   nid        = (const int*)  d_in[0];
    const int*   z          = (const int*)  d_in[1];
    const int*   src        = (const int*)  d_in[2];
    const int*   dst        = (const int*)  d_in[3];
    const int*   graph_id   = (const int*)  d_in[4];
    const float* init_embed = (const float*)d_in[5];
    const float* z_table    = (const float*)d_in[6];
    const float* W0 = (const float*)d_in[7];
    const float* b0 = (const float*)d_in[8];
    const float* W1 = (const float*)d_in[9];
    const float* b1 = (const float*)d_in[10];
    const float* W2 = (const float*)d_in[11];
    const float* b2 = (const float*)d_in[12];
    const float* lin1_W = (const float*)d_in[13];
    const float* lin1_b = (const float*)d_in[14];
    const float* lin2_W = (const float*)d_in[15];
    const float* lin2_b = (const float*)d_in[16];
    float* out = (float*)d_out;

    const int n = in_sizes[0];       // 50000
    const int E = in_sizes[2];       // 800000
    const int nb = (n + SCAN_B - 1) / SCAN_B;   // 49

    cudaFuncSetAttribute(k_gemm_h, cudaFuncAttributeMaxDynamicSharedMemorySize, GEMM_SMEM);

    // 1) weights fp16 + degree histogram (one kernel, disjoint block ranges)
    int deg_blocks = ((E >> 2) + 255) / 256;
    k_prep<<<WCONV_BLOCKS + deg_blocks, 256>>>(W0, W1, W2, src, dst, E, n);

    // 2) fused scan (norms + CSR row offsets) with in-kernel grid barrier
    k_scan<<<nb, SCAN_B>>>(n, nb);

    // 3) CSR fill + node features (one kernel, disjoint block ranges)
    int feat_blocks = (n * 32 + 255) / 256;
    k_build<<<FILL_BLOCKS + feat_blocks, 256>>>(src, dst, E, 2 * n,
                                                nid, z, init_embed, z_table, n);

    // 4) 3 GCN layers: spmm (g_xh -> g_aggh), hmma gemm (g_aggh -> g_xh)
    const int spmm_blocks = (n + 15) / 16;
    const int gemm_blocks = (n + 127) / 128;
    k_spmm<<<spmm_blocks, 256>>>(n);
    k_gemm_h<<<gemm_blocks, 256, GEMM_SMEM>>>(0, b0, n, 1);
    k_spmm<<<spmm_blocks, 256>>>(n);
    k_gemm_h<<<gemm_blocks, 256, GEMM_SMEM>>>(1, b1, n, 1);
    k_spmm<<<spmm_blocks, 256>>>(n);
    k_gemm_h<<<gemm_blocks, 256, GEMM_SMEM>>>(2, b2, n, 0);

    // 5) fused pooling + MLP head
    k_pool_mlp<<<G_CNT, 256>>>(graph_id, n, lin1_W, lin1_b, lin2_W, lin2_b, out);
}

// round 9
// speedup vs baseline: 2.1918x; 1.0013x over previous
#include <cuda_runtime.h>
#include <cuda_fp16.h>
#include <cstdint>

#define N_MAX   50000
#define E_MAX   800000
#define G_CNT   512
#define FDIM    128
#define OUTD    200
#define SCAN_B  1024
#define AP      136                    // smem pitch in halves (conflict-free ldmatrix)
#define GEMM_SMEM (2 * 128 * AP * 2)   // A tile + W tile, bytes
#define WCONV_BLOCKS 64                // 64*256 = 16384 = FDIM*FDIM
#define FILL_BLOCKS  784               // 784*256 = 200704 >= 2n and >= E/4

// ---------------- device scratch (static, no allocation) ----------------
__device__ __align__(128) __half g_xh[N_MAX * FDIM];    // half features; also final-layer output for pooling
__device__ __align__(128) __half g_aggh[N_MAX * FDIM];  // half aggregated (GEMM input)
__device__ __align__(128) __half g_Wh[3 * FDIM * FDIM]; // fp16 layer weights
__device__ int   g_deg[2 * N_MAX];
__device__ float g_norm_out[N_MAX];
__device__ float g_norm_in[N_MAX];
__device__ int   g_row_off[N_MAX + 1];
__device__ int   g_cursor[N_MAX];
__device__ int   g_esrc[E_MAX];
__device__ int   g_bsum[64];
__device__ unsigned g_count = 0;            // grid-barrier arrivals
__device__ volatile unsigned g_gen = 0;     // grid-barrier generation (monotonic across replays)

// ---------------- k_prep: fp16 weight conversion + degree histogram ----------------
__global__ void k_prep(const float* __restrict__ W0, const float* __restrict__ W1,
                       const float* __restrict__ W2,
                       const int* __restrict__ src, const int* __restrict__ dst,
                       int E, int n) {
    if (blockIdx.x < WCONV_BLOCKS) {
        int i = blockIdx.x * 256 + threadIdx.x;   // exactly FDIM*FDIM threads
        g_Wh[i]                   = __float2half_rn(__ldg(&W0[i]));
        g_Wh[FDIM * FDIM + i]     = __float2half_rn(__ldg(&W1[i]));
        g_Wh[2 * FDIM * FDIM + i] = __float2half_rn(__ldg(&W2[i]));
    } else {
        const int4* s4 = (const int4*)src;
        const int4* d4 = (const int4*)dst;
        int e4 = E >> 2;
        int nb = gridDim.x - WCONV_BLOCKS;
        int t = (blockIdx.x - WCONV_BLOCKS) * 256 + threadIdx.x;
        for (int i = t; i < e4; i += nb * 256) {
            int4 a = __ldg(&s4[i]);
            int4 b = __ldg(&d4[i]);
            atomicAdd(&g_deg[a.x], 1); atomicAdd(&g_deg[a.y], 1);
            atomicAdd(&g_deg[a.z], 1); atomicAdd(&g_deg[a.w], 1);
            atomicAdd(&g_deg[n + b.x], 1); atomicAdd(&g_deg[n + b.y], 1);
            atomicAdd(&g_deg[n + b.z], 1); atomicAdd(&g_deg[n + b.w], 1);
        }
        int base = e4 << 2;
        if (t < E - base) {
            atomicAdd(&g_deg[src[base + t]], 1);
            atomicAdd(&g_deg[n + dst[base + t]], 1);
        }
    }
}

// ---------------- k_scan: fused two-phase scan with software grid barrier ----------------
__global__ void __launch_bounds__(SCAN_B) k_scan(int n, int nb) {
    __shared__ int wsum[32];
    const int tid = threadIdx.x, lane = tid & 31, wid = tid >> 5;
    const int i = blockIdx.x * SCAN_B + tid;

    int v = 0;
    if (i < n) {
        v = g_deg[n + i];
        g_cursor[i] = 0;
        g_norm_out[i] = rsqrtf(fmaxf((float)g_deg[i], 1.0f));
        g_norm_in[i]  = rsqrtf(fmaxf((float)v, 1.0f));
    }
    int x = v;
    #pragma unroll
    for (int off = 1; off < 32; off <<= 1) {
        int t = __shfl_up_sync(0xffffffffu, x, off);
        if (lane >= off) x += t;
    }
    if (lane == 31) wsum[wid] = x;
    __syncthreads();
    if (wid == 0) {
        int w = wsum[lane];
        #pragma unroll
        for (int off = 1; off < 32; off <<= 1) {
            int t = __shfl_up_sync(0xffffffffu, w, off);
            if (lane >= off) w += t;
        }
        wsum[lane] = w;
    }
    __syncthreads();
    int incl = x + (wid > 0 ? wsum[wid - 1] : 0);
    if (i < n) g_row_off[i + 1] = incl;
    if (tid == SCAN_B - 1) g_bsum[blockIdx.x] = incl;
    if (i == 0) g_row_off[0] = 0;

    // grid barrier (generation counter; deterministic across replays)
    __syncthreads();
    __threadfence();
    if (tid == 0) {
        unsigned gen = g_gen;
        if (atomicAdd(&g_count, 1u) == gridDim.x - 1) {
            g_count = 0;
            __threadfence();
            g_gen = gen + 1;
        } else {
            while (g_gen == gen) { }
        }
    }
    __syncthreads();
    __threadfence();

    __shared__ int soff;
    if (tid < 32) {
        int l = tid;
        int bid = blockIdx.x;
        int s = (l < nb && l < bid) ? g_bsum[l] : 0;
        if (l + 32 < nb && l + 32 < bid) s += g_bsum[l + 32];
        #pragma unroll
        for (int off = 16; off > 0; off >>= 1)
            s += __shfl_down_sync(0xffffffffu, s, off);
        if (l == 0) soff = s;
    }
    __syncthreads();
    if (i < n) g_row_off[i + 1] += soff;
}

// ---------------- k_build: CSR fill (vectorized) + node features, overlapped ----------------
__global__ void k_build(const int* __restrict__ src, const int* __restrict__ dst,
                        int E, int n2,
                        const int* __restrict__ nid, const int* __restrict__ z,
                        const float* __restrict__ init_embed,
                        const float* __restrict__ z_table, int n) {
    if (blockIdx.x < FILL_BLOCKS) {
        int t = blockIdx.x * 256 + threadIdx.x;
        if (t < n2) g_deg[t] = 0;                 // deg is dead; re-zero for next call
        const int4* s4 = (const int4*)src;
        const int4* d4 = (const int4*)dst;
        int e4 = E >> 2;
        for (int i = t; i < e4; i += FILL_BLOCKS * 256) {
            int4 a = __ldg(&s4[i]);
            int4 b = __ldg(&d4[i]);
            g_esrc[g_row_off[b.x] + atomicAdd(&g_cursor[b.x], 1)] = a.x;
            g_esrc[g_row_off[b.y] + atomicAdd(&g_cursor[b.y], 1)] = a.y;
            g_esrc[g_row_off[b.z] + atomicAdd(&g_cursor[b.z], 1)] = a.z;
            g_esrc[g_row_off[b.w] + atomicAdd(&g_cursor[b.w], 1)] = a.w;
        }
        int base = e4 << 2;
        if (t < E - base) {
            int d = dst[base + t];
            g_esrc[g_row_off[d] + atomicAdd(&g_cursor[d], 1)] = src[base + t];
        }
    } else {
        int total = n * 32;
        int nb = gridDim.x - FILL_BLOCKS;
        for (int idx = (blockIdx.x - FILL_BLOCKS) * 256 + threadIdx.x; idx < total;
             idx += nb * 256) {
            int node = idx >> 5, q = idx & 31;
            float4 v;
            if (q < 16) v = __ldg(&((const float4*)init_embed)[(long)nid[node] * 16 + q]);
            else        v = __ldg(&((const float4*)z_table)[(long)z[node] * 16 + (q - 16)]);
            float s = g_norm_out[node];
            __half2 h0 = __floats2half2_rn(v.x * s, v.y * s);
            __half2 h1 = __floats2half2_rn(v.z * s, v.w * s);
            uint2 pk;
            pk.x = *(unsigned*)&h0;
            pk.y = *(unsigned*)&h1;
            ((uint2*)g_xh)[node * 32 + q] = pk;
        }
    }
}

// ---------------- SpMM gather-reduce: half-warp per dst row ----------------
// Pairwise fp16 reduction tree over the 4 gathered rows (12 HADD2), then
// 8 cvt + 8 FADD into fp32 accumulators -> 28 fma-pipe ops/iter (was 48).
__global__ void __launch_bounds__(256) k_spmm(int n) {
    int row = blockIdx.x * 16 + (threadIdx.x >> 4);
    int hl  = threadIdx.x & 15;
    if (row >= n) return;
    int e0 = g_row_off[row], e1 = g_row_off[row + 1];
    const uint4* xh = (const uint4*)g_xh;   // 16 uint4 per row
    float a0 = 0.f, a1 = 0.f, a2 = 0.f, a3 = 0.f, a4 = 0.f, a5 = 0.f, a6 = 0.f, a7 = 0.f;
    int e = e0;
    for (; e + 3 < e1; e += 4) {
        int s0 = __ldg(&g_esrc[e]);
        int s1 = __ldg(&g_esrc[e + 1]);
        int s2 = __ldg(&g_esrc[e + 2]);
        int s3 = __ldg(&g_esrc[e + 3]);
        uint4 p0 = __ldg(&xh[s0 * 16 + hl]);
        uint4 p1 = __ldg(&xh[s1 * 16 + hl]);
        uint4 p2 = __ldg(&xh[s2 * 16 + hl]);
        uint4 p3 = __ldg(&xh[s3 * 16 + hl]);
        // fp16 pairwise tree: t = (p0+p1) + (p2+p3) per half2 component
        __half2 t0 = __hadd2(__hadd2(*(__half2*)&p0.x, *(__half2*)&p1.x),
                             __hadd2(*(__half2*)&p2.x, *(__half2*)&p3.x));
        __half2 t1 = __hadd2(__hadd2(*(__half2*)&p0.y, *(__half2*)&p1.y),
                             __hadd2(*(__half2*)&p2.y, *(__half2*)&p3.y));
        __half2 t2 = __hadd2(__hadd2(*(__half2*)&p0.z, *(__half2*)&p1.z),
                             __hadd2(*(__half2*)&p2.z, *(__half2*)&p3.z));
        __half2 t3 = __hadd2(__hadd2(*(__half2*)&p0.w, *(__half2*)&p1.w),
                             __hadd2(*(__half2*)&p2.w, *(__half2*)&p3.w));
        float2 f;
        f = __half22float2(t0); a0 += f.x; a1 += f.y;
        f = __half22float2(t1); a2 += f.x; a3 += f.y;
        f = __half22float2(t2); a4 += f.x; a5 += f.y;
        f = __half22float2(t3); a6 += f.x; a7 += f.y;
    }
    for (; e < e1; e++) {
        int s0 = __ldg(&g_esrc[e]);
        uint4 p0 = __ldg(&xh[s0 * 16 + hl]);
        float2 f;
        f = __half22float2(*(__half2*)&p0.x); a0 += f.x; a1 += f.y;
        f = __half22float2(*(__half2*)&p0.y); a2 += f.x; a3 += f.y;
        f = __half22float2(*(__half2*)&p0.z); a4 += f.x; a5 += f.y;
        f = __half22float2(*(__half2*)&p0.w); a6 += f.x; a7 += f.y;
    }
    float ni = g_norm_in[row];
    __half2 h0 = __floats2half2_rn(a0 * ni, a1 * ni);
    __half2 h1 = __floats2half2_rn(a2 * ni, a3 * ni);
    __half2 h2 = __floats2half2_rn(a4 * ni, a5 * ni);
    __half2 h3 = __floats2half2_rn(a6 * ni, a7 * ni);
    uint4 pk;
    pk.x = *(unsigned*)&h0;
    pk.y = *(unsigned*)&h1;
    pk.z = *(unsigned*)&h2;
    pk.w = *(unsigned*)&h3;
    ((uint4*)g_aggh)[row * 16 + hl] = pk;
}

// ---------------- HMMA GEMM: out = act(g_aggh @ g_Wh[layer] + b) ----------------
__global__ void __launch_bounds__(256) k_gemm_h(int layer,
                                                const float* __restrict__ bias,
                                                int n, int mode) {
    extern __shared__ __half sh[];
    __half* As = sh;               // [128][AP]
    __half* Ws = sh + 128 * AP;    // [128][AP]
    const int tid = threadIdx.x;
    const int w = tid >> 5, lane = tid & 31;
    const int row0 = blockIdx.x * 128;

    {
        const uint4* asrc = (const uint4*)g_aggh;
        const uint4* wsrc = (const uint4*)(g_Wh + layer * FDIM * FDIM);
        int r = tid >> 1;
        int s0 = (tid & 1) * 8;
        int grow = row0 + r;
        #pragma unroll
        for (int s = 0; s < 8; s++) {
            uint4 av = make_uint4(0u, 0u, 0u, 0u);
            if (grow < n) av = __ldg(&asrc[grow * 16 + s0 + s]);
            *(uint4*)&As[r * AP + (s0 + s) * 8] = av;
            uint4 wv = __ldg(&wsrc[r * 16 + s0 + s]);
            *(uint4*)&Ws[r * AP + (s0 + s) * 8] = wv;
        }
    }
    __syncthreads();

    float acc[16][4];
    #pragma unroll
    for (int nt = 0; nt < 16; nt++)
        #pragma unroll
        for (int q = 0; q < 4; q++) acc[nt][q] = 0.f;

    #pragma unroll
    for (int kk = 0; kk < 8; kk++) {
        unsigned a0, a1, a2, a3;
        {
            int arow = 16 * w + (lane & 15);
            int acol = kk * 16 + ((lane >> 4) << 3);
            unsigned aaddr = (unsigned)__cvta_generic_to_shared(&As[arow * AP + acol]);
            asm volatile("ldmatrix.sync.aligned.m8n8.x4.shared.b16 {%0,%1,%2,%3}, [%4];"
                         : "=r"(a0), "=r"(a1), "=r"(a2), "=r"(a3) : "r"(aaddr));
        }
        int brow = kk * 16 + (lane & 15);
        unsigned bbase = (unsigned)__cvta_generic_to_shared(&Ws[brow * AP]);
        #pragma unroll
        for (int nt = 0; nt < 16; nt++) {
            unsigned b0, b1;
            asm volatile("ldmatrix.sync.aligned.m8n8.x2.trans.shared.b16 {%0,%1}, [%2];"
                         : "=r"(b0), "=r"(b1) : "r"(bbase + nt * 16u));
            asm volatile("mma.sync.aligned.m16n8k16.row.col.f32.f16.f16.f32 "
                         "{%0,%1,%2,%3}, {%4,%5,%6,%7}, {%8,%9}, {%0,%1,%2,%3};"
                         : "+f"(acc[nt][0]), "+f"(acc[nt][1]), "+f"(acc[nt][2]), "+f"(acc[nt][3])
                         : "r"(a0), "r"(a1), "r"(a2), "r"(a3), "r"(b0), "r"(b1));
        }
    }

    const int rlo = row0 + 16 * w + (lane >> 2);
    const int rhi = rlo + 8;
    const int cbase = (lane & 3) * 2;
    float slo = 1.f, shi = 1.f;
    if (mode) {
        if (rlo < n) slo = g_norm_out[rlo];
        if (rhi < n) shi = g_norm_out[rhi];
    }
    #pragma unroll
    for (int nt = 0; nt < 16; nt++) {
        int c = nt * 8 + cbase;
        float b0v = __ldg(&bias[c]), b1v = __ldg(&bias[c + 1]);
        if (rlo < n) {
            float v0 = acc[nt][0] + b0v, v1 = acc[nt][1] + b1v;
            if (mode) { v0 = fmaxf(v0, 0.f) * slo; v1 = fmaxf(v1, 0.f) * slo; }
            __half2 h = __floats2half2_rn(v0, v1);
            *(__half2*)&g_xh[rlo * FDIM + c] = h;
        }
        if (rhi < n) {
            float v2 = acc[nt][2] + b0v, v3 = acc[nt][3] + b1v;
            if (mode) { v2 = fmaxf(v2, 0.f) * shi; v3 = fmaxf(v3, 0.f) * shi; }
            __half2 h = __floats2half2_rn(v2, v3);
            *(__half2*)&g_xh[rhi * FDIM + c] = h;
        }
    }
}

// ---------------- fused pooling + MLP head (reads g_xh half, fp32 accumulate) ----------------
__global__ void __launch_bounds__(256) k_pool_mlp(const int* __restrict__ gid, int n,
                                                  const float* __restrict__ lin1_W,
                                                  const float* __restrict__ lin1_b,
                                                  const float* __restrict__ lin2_W,
                                                  const float* __restrict__ lin2_b,
                                                  float* __restrict__ out) {
    __shared__ float gs[FDIM];
    __shared__ float hs[FDIM];
    __shared__ int s_lo, s_hi;
    const int g = blockIdx.x;
    const int tid = threadIdx.x;

    if (tid == 0) {
        int lo = 0, hi = n;
        while (lo < hi) { int m = (lo + hi) >> 1; if (__ldg(&gid[m]) < g) lo = m + 1; else hi = m; }
        s_lo = lo;
    } else if (tid == 32) {
        int lo = 0, hi = n;
        while (lo < hi) { int m = (lo + hi) >> 1; if (__ldg(&gid[m]) <= g) lo = m + 1; else hi = m; }
        s_hi = lo;
    }
    __syncthreads();

    const int lo = s_lo, hi = s_hi;
    if (tid < 64) {
        float acc0 = 0.f, acc1 = 0.f;
        const __half2* xh2 = (const __half2*)g_xh;
        for (int node = lo; node < hi; node++) {
            float2 f = __half22float2(xh2[node * 64 + tid]);
            acc0 += f.x; acc1 += f.y;
        }
        gs[2 * tid] = acc0;
        gs[2 * tid + 1] = acc1;
    }
    __syncthreads();
    if (tid < FDIM) {
        float acc = __ldg(&lin1_b[tid]);
        #pragma unroll 8
        for (int k = 0; k < FDIM; k++)
            acc += gs[k] * __ldg(&lin1_W[k * FDIM + tid]);
        hs[tid] = fmaxf(acc, 0.f);
    }
    __syncthreads();
    for (int c = tid; c < OUTD; c += blockDim.x) {
        float acc = __ldg(&lin2_b[c]);
        #pragma unroll 8
        for (int k = 0; k < FDIM; k++)
            acc += hs[k] * __ldg(&lin2_W[k * OUTD + c]);
        out[g * OUTD + c] = acc;
    }
}

// ---------------- launch ----------------
extern "C" void kernel_launch(void* const* d_in, const int* in_sizes, int n_in,
                              void* d_out, int out_size) {
    const int*   nid        = (const int*)  d_in[0];
    const int*   z          = (const int*)  d_in[1];
    const int*   src        = (const int*)  d_in[2];
    const int*   dst        = (const int*)  d_in[3];
    const int*   graph_id   = (const int*)  d_in[4];
    const float* init_embed = (const float*)d_in[5];
    const float* z_table    = (const float*)d_in[6];
    const float* W0 = (const float*)d_in[7];
    const float* b0 = (const float*)d_in[8];
    const float* W1 = (const float*)d_in[9];
    const float* b1 = (const float*)d_in[10];
    const float* W2 = (const float*)d_in[11];
    const float* b2 = (const float*)d_in[12];
    const float* lin1_W = (const float*)d_in[13];
    const float* lin1_b = (const float*)d_in[14];
    const float* lin2_W = (const float*)d_in[15];
    const float* lin2_b = (const float*)d_in[16];
    float* out = (float*)d_out;

    const int n = in_sizes[0];       // 50000
    const int E = in_sizes[2];       // 800000
    const int nb = (n + SCAN_B - 1) / SCAN_B;   // 49

    cudaFuncSetAttribute(k_gemm_h, cudaFuncAttributeMaxDynamicSharedMemorySize, GEMM_SMEM);

    // 1) weights fp16 + degree histogram (one kernel, disjoint block ranges)
    int deg_blocks = ((E >> 2) + 255) / 256;
    k_prep<<<WCONV_BLOCKS + deg_blocks, 256>>>(W0, W1, W2, src, dst, E, n);

    // 2) fused scan (norms + CSR row offsets) with in-kernel grid barrier
    k_scan<<<nb, SCAN_B>>>(n, nb);

    // 3) CSR fill + node features (one kernel, disjoint block ranges)
    int feat_blocks = (n * 32 + 255) / 256;
    k_build<<<FILL_BLOCKS + feat_blocks, 256>>>(src, dst, E, 2 * n,
                                                nid, z, init_embed, z_table, n);

    // 4) 3 GCN layers: spmm (g_xh -> g_aggh), hmma gemm (g_aggh -> g_xh)
    const int spmm_blocks = (n + 15) / 16;
    const int gemm_blocks = (n + 127) / 128;
    k_spmm<<<spmm_blocks, 256>>>(n);
    k_gemm_h<<<gemm_blocks, 256, GEMM_SMEM>>>(0, b0, n, 1);
    k_spmm<<<spmm_blocks, 256>>>(n);
    k_gemm_h<<<gemm_blocks, 256, GEMM_SMEM>>>(1, b1, n, 1);
    k_spmm<<<spmm_blocks, 256>>>(n);
    k_gemm_h<<<gemm_blocks, 256, GEMM_SMEM>>>(2, b2, n, 0);

    // 5) fused pooling + MLP head
    k_pool_mlp<<<G_CNT, 256>>>(graph_id, n, lin1_W, lin1_b, lin2_W, lin2_b, out);
}